// round 8
// baseline (speedup 1.0000x reference)
#include <cuda_runtime.h>
#include <cuda_bf16.h>

// Problem constants
#define Bq 2
#define Sq 2048
#define Dq 1024
#define Hq 16
#define HDq 64
#define Mq (Bq * Sq)   // 4096
#define GK Dq          // 1024

// Scratch (device globals: allocation-free)
__device__ float g_q[Bq * Hq * Sq * HDq];    // [b][h][s][hd]
__device__ float g_k[Bq * Hq * Sq * HDq];
__device__ float g_v[Bq * Hq * Sq * HDq];
__device__ float g_att[Mq * Dq];             // [b*s][d]

// ---------------------------------------------------------------------------
// TF32 helpers
// ---------------------------------------------------------------------------
__device__ __forceinline__ float tf32r(float x) {
    unsigned u;
    asm("cvt.rna.tf32.f32 %0, %1;" : "=r"(u) : "f"(x));
    return __uint_as_float(u);
}

__device__ __forceinline__ void mma_tf32(float c[4], const unsigned a[4],
                                         const unsigned b[2]) {
    asm volatile(
        "mma.sync.aligned.m16n8k8.row.col.f32.tf32.tf32.f32 "
        "{%0,%1,%2,%3}, {%4,%5,%6,%7}, {%8,%9}, {%0,%1,%2,%3};\n"
        : "+f"(c[0]), "+f"(c[1]), "+f"(c[2]), "+f"(c[3])
        : "r"(a[0]), "r"(a[1]), "r"(a[2]), "r"(a[3]),
          "r"(b[0]), "r"(b[1]));
}

// ===========================================================================
// TF32 GEMM, NT: C[m,n] = sum_k A[m,k]*W[n,k] + bias[n]
// BM=BN=128, BK=32, 512 threads = 16 warps (4m x 4n), warp tile 32x32.
// Double-buffered smem + register prefetch. Interleaved 8-column groups
// (col c -> (c&3)*2 + (c>>2)) so (t, t+4) fragment pairs load as LDS.64.
// grid.z selects one of up to 3 independent GEMMs (fused QKV).
// ===========================================================================
#define GST 40
#define GEMM_SMEM (4 * 128 * GST * 4)   // 2 bufs x (A+W) x 128 x GST floats

__global__ __launch_bounds__(512) void gemm_tf32(
    const float* A0, const float* W0, const float* B0, float* C0,
    const float* A1, const float* W1, const float* B1, float* C1,
    const float* A2, const float* W2, const float* B2, float* C2,
    int head_major)
{
    extern __shared__ float sm[];
    const float* A; const float* W; const float* bias; float* C;
    if (blockIdx.z == 0)      { A = A0; W = W0; bias = B0; C = C0; }
    else if (blockIdx.z == 1) { A = A1; W = W1; bias = B1; C = C1; }
    else                      { A = A2; W = W2; bias = B2; C = C2; }

    const int tid  = threadIdx.x;
    const int warp = tid >> 5;        // 0..15
    const int lane = tid & 31;
    const int g    = lane >> 2;
    const int t    = lane & 3;
    const int wm   = (warp >> 2) * 32;
    const int wn   = (warp & 3) * 32;
    const int m0   = blockIdx.y * 128;
    const int n0   = blockIdx.x * 128;

    const int r0 = tid >> 2;          // 0..127 (one row per thread per matrix)
    const int kg = tid & 3;           // k-group 0..3

    float acc[2][4][4] = {};
    float4 ra[2], rw[2];

    const float* pa = A + (size_t)(m0 + r0) * GK + kg * 8;
    const float* pw = W + (size_t)(n0 + r0) * GK + kg * 8;

    // --- prefetch k0 = 0 ---
    ra[0] = *(const float4*)pa; ra[1] = *(const float4*)(pa + 4);
    rw[0] = *(const float4*)pw; rw[1] = *(const float4*)(pw + 4);

    // store buf 0 (interleaved + tf32)
    {
        float* da = sm + (size_t)(0 * 128 + r0) * GST + kg * 8;
        float* dw = sm + (size_t)(2 * 128 + r0) * GST + kg * 8;
        *(float4*)da = make_float4(tf32r(ra[0].x), tf32r(ra[1].x),
                                   tf32r(ra[0].y), tf32r(ra[1].y));
        *(float4*)(da + 4) = make_float4(tf32r(ra[0].z), tf32r(ra[1].z),
                                         tf32r(ra[0].w), tf32r(ra[1].w));
        *(float4*)dw = make_float4(tf32r(rw[0].x), tf32r(rw[1].x),
                                   tf32r(rw[0].y), tf32r(rw[1].y));
        *(float4*)(dw + 4) = make_float4(tf32r(rw[0].z), tf32r(rw[1].z),
                                         tf32r(rw[0].w), tf32r(rw[1].w));
    }
    __syncthreads();

    int buf = 0;
    for (int k0 = 0; k0 < GK; k0 += 32) {
        const bool more = (k0 + 32 < GK);
        if (more) {
            ra[0] = *(const float4*)(pa + k0 + 32);
            ra[1] = *(const float4*)(pa + k0 + 36);
            rw[0] = *(const float4*)(pw + k0 + 32);
            rw[1] = *(const float4*)(pw + k0 + 36);
        }

        const float* As = sm + (size_t)buf * 128 * GST;
        const float* Ws = sm + (size_t)(2 + buf) * 128 * GST;
        #pragma unroll
        for (int ks = 0; ks < 4; ks++) {
            const int kc = ks * 8 + 2 * t;
            unsigned af[2][4];
            #pragma unroll
            for (int i = 0; i < 2; i++) {
                float2 p0 = *(const float2*)(As + (wm + i * 16 + g) * GST + kc);
                float2 p1 = *(const float2*)(As + (wm + i * 16 + g + 8) * GST + kc);
                af[i][0] = __float_as_uint(p0.x);
                af[i][1] = __float_as_uint(p1.x);
                af[i][2] = __float_as_uint(p0.y);
                af[i][3] = __float_as_uint(p1.y);
            }
            #pragma unroll
            for (int j = 0; j < 4; j++) {
                float2 pb = *(const float2*)(Ws + (wn + j * 8 + g) * GST + kc);
                unsigned bf[2] = { __float_as_uint(pb.x), __float_as_uint(pb.y) };
                mma_tf32(acc[0][j], af[0], bf);
                mma_tf32(acc[1][j], af[1], bf);
            }
        }

        if (more) {
            const int ob = buf ^ 1;
            float* da = sm + (size_t)(ob * 128 + r0) * GST + kg * 8;
            float* dw = sm + (size_t)((2 + ob) * 128 + r0) * GST + kg * 8;
            *(float4*)da = make_float4(tf32r(ra[0].x), tf32r(ra[1].x),
                                       tf32r(ra[0].y), tf32r(ra[1].y));
            *(float4*)(da + 4) = make_float4(tf32r(ra[0].z), tf32r(ra[1].z),
                                             tf32r(ra[0].w), tf32r(ra[1].w));
            *(float4*)dw = make_float4(tf32r(rw[0].x), tf32r(rw[1].x),
                                       tf32r(rw[0].y), tf32r(rw[1].y));
            *(float4*)(dw + 4) = make_float4(tf32r(rw[0].z), tf32r(rw[1].z),
                                             tf32r(rw[0].w), tf32r(rw[1].w));
        }
        __syncthreads();
        buf ^= 1;
    }

    // Epilogue: acc[i][j] rows (wm+16i+g, +8), cols (wn+8j+2t, +1)
    #pragma unroll
    for (int i = 0; i < 2; i++) {
        #pragma unroll
        for (int j = 0; j < 4; j++) {
            int mrow = m0 + wm + i * 16 + g;
            int ncol = n0 + wn + j * 8 + t * 2;
            float b0 = bias[ncol], b1 = bias[ncol + 1];
            float2 lo = make_float2(acc[i][j][0] + b0, acc[i][j][1] + b1);
            float2 hi = make_float2(acc[i][j][2] + b0, acc[i][j][3] + b1);
            if (head_major) {
                int hh = ncol >> 6, hd = ncol & 63;
                size_t a0 = ((((size_t)(mrow >> 11) * Hq + hh) << 11)
                             + (mrow & 2047)) * HDq + hd;
                int mr2 = mrow + 8;
                size_t a1 = ((((size_t)(mr2 >> 11) * Hq + hh) << 11)
                             + (mr2 & 2047)) * HDq + hd;
                *(float2*)(C + a0) = lo;
                *(float2*)(C + a1) = hi;
            } else {
                *(float2*)(C + (size_t)mrow * GK + ncol) = lo;
                *(float2*)(C + (size_t)(mrow + 8) * GK + ncol) = hi;
            }
        }
    }
}

// ===========================================================================
// TF32 flash attention (unchanged from R6): 128 queries/block, 4 warps x 32
// rows (2 x m16), 64-key tiles.
// ===========================================================================
#define KST 72
#define PST 68
#define ATTN_SMEM ((2 * 64 * KST + 128 * PST) * 4)

__global__ __launch_bounds__(128) void attn_mma()
{
    extern __shared__ float sm[];
    float* Ks = sm;                       // [64][KST] interleaved cols (hd)
    float* Vs = sm + 64 * KST;            // [64][KST] plain [key][hd]
    float* Ps = sm + 2 * 64 * KST;        // [128][PST]: Q staging, then P

    const int bh   = blockIdx.y;
    const int q0   = blockIdx.x * 128;
    const int b    = bh >> 4;
    const int h    = bh & 15;
    const int tid  = threadIdx.x;
    const int warp = tid >> 5;
    const int lane = tid & 31;
    const int g    = lane >> 2;
    const int t    = lane & 3;
    const int wm   = warp * 32;

    const float* gq = g_q + (((size_t)bh) << 11) * HDq;
    const float* gk = g_k + (((size_t)bh) << 11) * HDq;
    const float* gv = g_v + (((size_t)bh) << 11) * HDq;

    #pragma unroll
    for (int m = 0; m < 8; m++) {
        int task = tid + m * 128;
        int r = task >> 3, kgq = task & 7;
        const float* src = gq + (size_t)(q0 + r) * HDq + kgq * 8;
        float4 v0 = *(const float4*)src;
        float4 v1 = *(const float4*)(src + 4);
        float* dst = Ps + r * PST + kgq * 8;
        *(float4*)dst = make_float4(tf32r(v0.x * 0.125f), tf32r(v1.x * 0.125f),
                                    tf32r(v0.y * 0.125f), tf32r(v1.y * 0.125f));
        *(float4*)(dst + 4) = make_float4(tf32r(v0.z * 0.125f), tf32r(v1.z * 0.125f),
                                          tf32r(v0.w * 0.125f), tf32r(v1.w * 0.125f));
    }
    __syncthreads();

    unsigned qa[2][8][4];
    #pragma unroll
    for (int i = 0; i < 2; i++)
        #pragma unroll
        for (int k = 0; k < 8; k++) {
            float2 p0 = *(const float2*)(Ps + (wm + i * 16 + g) * PST + k * 8 + 2 * t);
            float2 p1 = *(const float2*)(Ps + (wm + i * 16 + g + 8) * PST + k * 8 + 2 * t);
            qa[i][k][0] = __float_as_uint(p0.x);
            qa[i][k][1] = __float_as_uint(p1.x);
            qa[i][k][2] = __float_as_uint(p0.y);
            qa[i][k][3] = __float_as_uint(p1.y);
        }
    __syncthreads();

    float oacc[2][8][4] = {};
    float mrow[2][2] = { {-1e30f, -1e30f}, {-1e30f, -1e30f} };
    float lrow[2][2] = { {0.f, 0.f}, {0.f, 0.f} };

    for (int tile = 0; tile < Sq / 64; tile++) {
        #pragma unroll
        for (int m = 0; m < 4; m++) {
            int task = tid + m * 128;
            int r = task >> 3, kgq = task & 7;
            const float* src = gk + (size_t)(tile * 64 + r) * HDq + kgq * 8;
            float4 v0 = *(const float4*)src;
            float4 v1 = *(const float4*)(src + 4);
            float* dst = Ks + r * KST + kgq * 8;
            *(float4*)dst = make_float4(tf32r(v0.x), tf32r(v1.x),
                                        tf32r(v0.y), tf32r(v1.y));
            *(float4*)(dst + 4) = make_float4(tf32r(v0.z), tf32r(v1.z),
                                              tf32r(v0.w), tf32r(v1.w));
        }
        #pragma unroll
        for (int m = 0; m < 8; m++) {
            int idx = tid + m * 128;
            int r = idx >> 4, c = (idx & 15) * 4;
            float4 v = *(const float4*)(gv + (size_t)(tile * 64 + r) * HDq + c);
            *(float4*)(Vs + r * KST + c) =
                make_float4(tf32r(v.x), tf32r(v.y), tf32r(v.z), tf32r(v.w));
        }
        __syncthreads();

        float sacc[2][8][4] = {};
        #pragma unroll
        for (int k = 0; k < 8; k++) {
            #pragma unroll
            for (int j = 0; j < 8; j++) {
                float2 pb = *(const float2*)(Ks + (j * 8 + g) * KST + k * 8 + 2 * t);
                unsigned bf[2] = { __float_as_uint(pb.x), __float_as_uint(pb.y) };
                mma_tf32(sacc[0][j], qa[0][k], bf);
                mma_tf32(sacc[1][j], qa[1][k], bf);
            }
        }

        #pragma unroll
        for (int i = 0; i < 2; i++) {
            float mx0 = -1e30f, mx1 = -1e30f;
            #pragma unroll
            for (int j = 0; j < 8; j++) {
                mx0 = fmaxf(mx0, fmaxf(sacc[i][j][0], sacc[i][j][1]));
                mx1 = fmaxf(mx1, fmaxf(sacc[i][j][2], sacc[i][j][3]));
            }
            mx0 = fmaxf(mx0, __shfl_xor_sync(0xffffffffu, mx0, 1));
            mx0 = fmaxf(mx0, __shfl_xor_sync(0xffffffffu, mx0, 2));
            mx1 = fmaxf(mx1, __shfl_xor_sync(0xffffffffu, mx1, 1));
            mx1 = fmaxf(mx1, __shfl_xor_sync(0xffffffffu, mx1, 2));

            float nm0 = fmaxf(mrow[i][0], mx0), nm1 = fmaxf(mrow[i][1], mx1);
            float a0 = __expf(mrow[i][0] - nm0), a1 = __expf(mrow[i][1] - nm1);
            mrow[i][0] = nm0; mrow[i][1] = nm1;

            float ps0 = 0.f, ps1 = 0.f;
            #pragma unroll
            for (int j = 0; j < 8; j++) {
                sacc[i][j][0] = __expf(sacc[i][j][0] - nm0);
                sacc[i][j][1] = __expf(sacc[i][j][1] - nm0);
                sacc[i][j][2] = __expf(sacc[i][j][2] - nm1);
                sacc[i][j][3] = __expf(sacc[i][j][3] - nm1);
                ps0 += sacc[i][j][0] + sacc[i][j][1];
                ps1 += sacc[i][j][2] + sacc[i][j][3];
            }
            ps0 += __shfl_xor_sync(0xffffffffu, ps0, 1);
            ps0 += __shfl_xor_sync(0xffffffffu, ps0, 2);
            ps1 += __shfl_xor_sync(0xffffffffu, ps1, 1);
            ps1 += __shfl_xor_sync(0xffffffffu, ps1, 2);
            lrow[i][0] = lrow[i][0] * a0 + ps0;
            lrow[i][1] = lrow[i][1] * a1 + ps1;

            #pragma unroll
            for (int j = 0; j < 8; j++) {
                oacc[i][j][0] *= a0; oacc[i][j][1] *= a0;
                oacc[i][j][2] *= a1; oacc[i][j][3] *= a1;
            }
        }

        #pragma unroll
        for (int i = 0; i < 2; i++)
            #pragma unroll
            for (int j = 0; j < 8; j++) {
                *(float2*)(Ps + (wm + i * 16 + g) * PST + j * 8 + 2 * t) =
                    make_float2(tf32r(sacc[i][j][0]), tf32r(sacc[i][j][1]));
                *(float2*)(Ps + (wm + i * 16 + g + 8) * PST + j * 8 + 2 * t) =
                    make_float2(tf32r(sacc[i][j][2]), tf32r(sacc[i][j][3]));
            }
        __syncwarp();

        #pragma unroll
        for (int k = 0; k < 8; k++) {
            unsigned pa[2][4];
            #pragma unroll
            for (int i = 0; i < 2; i++) {
                const float* pr0 = Ps + (wm + i * 16 + g) * PST + k * 8;
                const float* pr1 = Ps + (wm + i * 16 + g + 8) * PST + k * 8;
                pa[i][0] = __float_as_uint(pr0[t]);
                pa[i][1] = __float_as_uint(pr1[t]);
                pa[i][2] = __float_as_uint(pr0[t + 4]);
                pa[i][3] = __float_as_uint(pr1[t + 4]);
            }
            #pragma unroll
            for (int j = 0; j < 8; j++) {
                unsigned bf[2] = {
                    __float_as_uint(Vs[(k * 8 + t) * KST + j * 8 + g]),
                    __float_as_uint(Vs[(k * 8 + t + 4) * KST + j * 8 + g]) };
                mma_tf32(oacc[0][j], pa[0], bf);
                mma_tf32(oacc[1][j], pa[1], bf);
            }
        }
        __syncthreads();
    }

    #pragma unroll
    for (int i = 0; i < 2; i++) {
        float il0 = 1.0f / lrow[i][0], il1 = 1.0f / lrow[i][1];
        #pragma unroll
        for (int j = 0; j < 8; j++) {
            int r = q0 + wm + i * 16 + g;
            int col = h * HDq + j * 8 + 2 * t;
            size_t a0 = (size_t)(b * Sq + r) * Dq + col;
            size_t a1 = (size_t)(b * Sq + r + 8) * Dq + col;
            *(float2*)(g_att + a0) =
                make_float2(oacc[i][j][0] * il0, oacc[i][j][1] * il0);
            *(float2*)(g_att + a1) =
                make_float2(oacc[i][j][2] * il1, oacc[i][j][3] * il1);
        }
    }
}

// ---------------------------------------------------------------------------
// Launch.  Input order: xq, xv, xk, Wq, bq, Wk, bk, Wv, bv, Wo, bo
// ---------------------------------------------------------------------------
extern "C" void kernel_launch(void* const* d_in, const int* in_sizes, int n_in,
                              void* d_out, int out_size)
{
    const float* xq = (const float*)d_in[0];
    const float* xv = (const float*)d_in[1];
    const float* xk = (const float*)d_in[2];
    const float* Wq = (const float*)d_in[3];
    const float* bq = (const float*)d_in[4];
    const float* Wk = (const float*)d_in[5];
    const float* bk = (const float*)d_in[6];
    const float* Wv = (const float*)d_in[7];
    const float* bv = (const float*)d_in[8];
    const float* Wo = (const float*)d_in[9];
    const float* bo = (const float*)d_in[10];
    float* out = (float*)d_out;

    float *pq, *pk, *pv, *patt;
    cudaGetSymbolAddress((void**)&pq, g_q);
    cudaGetSymbolAddress((void**)&pk, g_k);
    cudaGetSymbolAddress((void**)&pv, g_v);
    cudaGetSymbolAddress((void**)&patt, g_att);

    static int attr_done = 0;
    if (!attr_done) {
        cudaFuncSetAttribute(gemm_tf32,
            cudaFuncAttributeMaxDynamicSharedMemorySize, GEMM_SMEM);
        cudaFuncSetAttribute(attn_mma,
            cudaFuncAttributeMaxDynamicSharedMemorySize, ATTN_SMEM);
        attr_done = 1;
    }

    // Fused Q/K/V projections
    dim3 gqkv(Dq / 128, Mq / 128, 3);     // (8, 32, 3)
    gemm_tf32<<<gqkv, 512, GEMM_SMEM>>>(
        xq, Wq, bq, pq,
        xk, Wk, bk, pk,
        xv, Wv, bv, pv, 1);

    dim3 gattn(Sq / 128, Bq * Hq);        // (16, 32)
    attn_mma<<<gattn, 128, ATTN_SMEM>>>();

    dim3 gproj(Dq / 128, Mq / 128, 1);    // (8, 32)
    gemm_tf32<<<gproj, 512, GEMM_SMEM>>>(
        patt, Wo, bo, out,
        patt, Wo, bo, out,
        patt, Wo, bo, out, 0);
}

// round 10
// speedup vs baseline: 1.9365x; 1.9365x over previous
#include <cuda_runtime.h>
#include <cstdint>

// Problem constants
#define Bq 2
#define Sq 2048
#define Dq 1024
#define Hq 16
#define HDq 64
#define Mq (Bq * Sq)   // 4096
#define GK Dq          // 1024

// Scratch (device globals: allocation-free)
__device__ float g_q[Bq * Hq * Sq * HDq];    // [b][h][s][hd] (tf32-rounded)
__device__ float g_k[Bq * Hq * Sq * HDq];
__device__ float g_v[Bq * Hq * Sq * HDq];
__device__ float g_att[Mq * Dq];             // [b*s][d]      (tf32-rounded)
__device__ float g_rx[3][Mq * Dq];           // rounded xq, xk, xv
__device__ float g_rw[4][Dq * Dq];           // rounded Wq, Wk, Wv, Wo

// ---------------------------------------------------------------------------
// Helpers
// ---------------------------------------------------------------------------
__device__ __forceinline__ float tf32r(float x) {
    unsigned u;
    asm("cvt.rna.tf32.f32 %0, %1;" : "=r"(u) : "f"(x));
    return __uint_as_float(u);
}

__device__ __forceinline__ void mma_tf32(float c[4], const unsigned a[4],
                                         const unsigned b[2]) {
    asm volatile(
        "mma.sync.aligned.m16n8k8.row.col.f32.tf32.tf32.f32 "
        "{%0,%1,%2,%3}, {%4,%5,%6,%7}, {%8,%9}, {%0,%1,%2,%3};\n"
        : "+f"(c[0]), "+f"(c[1]), "+f"(c[2]), "+f"(c[3])
        : "r"(a[0]), "r"(a[1]), "r"(a[2]), "r"(a[3]),
          "r"(b[0]), "r"(b[1]));
}

__device__ __forceinline__ uint32_t s2u(const void* p) {
    uint32_t a;
    asm("{ .reg .u64 t; cvta.to.shared.u64 t, %1; cvt.u32.u64 %0, t; }"
        : "=r"(a) : "l"(p));
    return a;
}

__device__ __forceinline__ void cp16(uint32_t dst, const void* src) {
    asm volatile("cp.async.cg.shared.global [%0], [%1], 16;"
                 :: "r"(dst), "l"(src) : "memory");
}
#define CP_COMMIT() asm volatile("cp.async.commit_group;" ::: "memory")
#define CP_WAIT0()  asm volatile("cp.async.wait_group 0;" ::: "memory")
#define CP_WAIT1()  asm volatile("cp.async.wait_group 1;" ::: "memory")

// ---------------------------------------------------------------------------
// Pre-round inputs/weights to tf32 (rna) once per launch.
// blockIdx.y: 0..2 -> xq/xk/xv, 3..6 -> Wq/Wk/Wv/Wo
// ---------------------------------------------------------------------------
__global__ __launch_bounds__(256) void round_tf32(
    const float* xq, const float* xk, const float* xv,
    const float* wq, const float* wk, const float* wv, const float* wo)
{
    const float* src; float* dst; int n4;
    switch (blockIdx.y) {
        case 0: src = xq; dst = g_rx[0]; n4 = Mq * Dq / 4; break;
        case 1: src = xk; dst = g_rx[1]; n4 = Mq * Dq / 4; break;
        case 2: src = xv; dst = g_rx[2]; n4 = Mq * Dq / 4; break;
        case 3: src = wq; dst = g_rw[0]; n4 = Dq * Dq / 4; break;
        case 4: src = wk; dst = g_rw[1]; n4 = Dq * Dq / 4; break;
        case 5: src = wv; dst = g_rw[2]; n4 = Dq * Dq / 4; break;
        default: src = wo; dst = g_rw[3]; n4 = Dq * Dq / 4; break;
    }
    for (int i = blockIdx.x * 256 + threadIdx.x; i < n4; i += gridDim.x * 256) {
        float4 v = ((const float4*)src)[i];
        ((float4*)dst)[i] = make_float4(tf32r(v.x), tf32r(v.y),
                                        tf32r(v.z), tf32r(v.w));
    }
}

// ===========================================================================
// TF32 GEMM, NT: C[m,n] = sum_k A[m,k]*W[n,k] + bias[n]
// Inputs pre-rounded to tf32. BM=BN=128, BK=32, 256 threads, 8 warps
// (4m x 2n), warp tile 32x64. 3-stage cp.async pipeline, plain smem layout
// stride 36 (conflict-free scalar fragment loads: bank = 4g+t+8ks).
// grid.z selects one of up to 3 independent GEMMs (fused QKV).
// head_major: write tf32-rounded to [b][h][s][hd]; else raw fp32 row-major.
// ===========================================================================
#define GST 36
#define GSTAGE 3
#define GEMM_SMEM (GSTAGE * 2 * 128 * GST * 4)   // 110592 B

__global__ __launch_bounds__(256) void gemm_cp(
    const float* A0, const float* W0, const float* B0, float* C0,
    const float* A1, const float* W1, const float* B1, float* C1,
    const float* A2, const float* W2, const float* B2, float* C2,
    int head_major)
{
    extern __shared__ float sm[];
    const float* A; const float* W; const float* bias; float* C;
    if (blockIdx.z == 0)      { A = A0; W = W0; bias = B0; C = C0; }
    else if (blockIdx.z == 1) { A = A1; W = W1; bias = B1; C = C1; }
    else                      { A = A2; W = W2; bias = B2; C = C2; }

    const int tid  = threadIdx.x;
    const int warp = tid >> 5;
    const int lane = tid & 31;
    const int g    = lane >> 2;
    const int t    = lane & 3;
    const int wm   = (warp >> 1) * 32;
    const int wn   = (warp & 1) * 64;
    const int m0   = blockIdx.y * 128;
    const int n0   = blockIdx.x * 128;

    const uint32_t smu = s2u(sm);
    const float* pa = A + (size_t)m0 * GK;
    const float* pw = W + (size_t)n0 * GK;
    // per-thread copy slots: idx = q*256 + tid, q = 0..3 -> row, col4
    const int cr = tid >> 3;          // base row (grows by 32 per q)
    const int cc = (tid & 7) * 4;     // float offset in row (0..28)

    float acc[2][8][4] = {};

    // stage(it, buf): copy A/W k-slab [*, it*32 .. +32) into buffer buf
    #define STAGE(it_, buf_)                                                   \
    do {                                                                       \
        const int kk = (it_) * 32;                                             \
        const uint32_t sa = smu + (uint32_t)(buf_) * (2 * 128 * GST * 4);      \
        const uint32_t sw = sa + 128 * GST * 4;                                \
        _Pragma("unroll")                                                      \
        for (int q = 0; q < 4; q++) {                                          \
            int r = cr + q * 32;                                               \
            cp16(sa + (r * GST + cc) * 4, pa + (size_t)r * GK + kk + cc);      \
            cp16(sw + (r * GST + cc) * 4, pw + (size_t)r * GK + kk + cc);      \
        }                                                                      \
    } while (0)

    STAGE(0, 0); CP_COMMIT();
    STAGE(1, 1); CP_COMMIT();

    for (int it = 0; it < 32; it++) {
        CP_WAIT1();            // stage `it` resident (for this thread)
        __syncthreads();       // ... for all threads; prior compute done
        if (it + 2 < 32) STAGE(it + 2, (it + 2) % 3);
        CP_COMMIT();

        const float* As = sm + (it % 3) * (2 * 128 * GST);
        const float* Ws = As + 128 * GST;
        #pragma unroll
        for (int ks = 0; ks < 4; ks++) {
            const int kc = ks * 8 + t;
            unsigned af[2][4];
            #pragma unroll
            for (int i = 0; i < 2; i++) {
                const float* ar = As + (wm + i * 16 + g) * GST;
                af[i][0] = __float_as_uint(ar[kc]);
                af[i][1] = __float_as_uint(ar[8 * GST + kc]);
                af[i][2] = __float_as_uint(ar[kc + 4]);
                af[i][3] = __float_as_uint(ar[8 * GST + kc + 4]);
            }
            #pragma unroll
            for (int j = 0; j < 8; j++) {
                const float* br = Ws + (wn + j * 8 + g) * GST;
                unsigned bf[2] = { __float_as_uint(br[kc]),
                                   __float_as_uint(br[kc + 4]) };
                mma_tf32(acc[0][j], af[0], bf);
                mma_tf32(acc[1][j], af[1], bf);
            }
        }
    }
    #undef STAGE

    // Epilogue
    #pragma unroll
    for (int i = 0; i < 2; i++) {
        #pragma unroll
        for (int j = 0; j < 8; j++) {
            int mrow = m0 + wm + i * 16 + g;
            int ncol = n0 + wn + j * 8 + t * 2;
            float b0 = bias[ncol], b1 = bias[ncol + 1];
            float2 lo = make_float2(acc[i][j][0] + b0, acc[i][j][1] + b1);
            float2 hi = make_float2(acc[i][j][2] + b0, acc[i][j][3] + b1);
            if (head_major) {
                lo = make_float2(tf32r(lo.x), tf32r(lo.y));
                hi = make_float2(tf32r(hi.x), tf32r(hi.y));
                int hh = ncol >> 6, hd = ncol & 63;
                size_t a0 = ((((size_t)(mrow >> 11) * Hq + hh) << 11)
                             + (mrow & 2047)) * HDq + hd;
                int mr2 = mrow + 8;
                size_t a1 = ((((size_t)(mr2 >> 11) * Hq + hh) << 11)
                             + (mr2 & 2047)) * HDq + hd;
                *(float2*)(C + a0) = lo;
                *(float2*)(C + a1) = hi;
            } else {
                *(float2*)(C + (size_t)mrow * GK + ncol) = lo;
                *(float2*)(C + (size_t)(mrow + 8) * GK + ncol) = hi;
            }
        }
    }
}

// ===========================================================================
// TF32 flash attention: 128 queries/block, 4 warps x 32 rows (2 x m16),
// 64-key tiles. cp.async staging of (pre-rounded) Q/K/V; plain layouts.
// K stride 68 (bank 4g+t+8k), V stride 72 (bank 8t+g+8j) — conflict-free.
// P phase unchanged from R6/R7.
// ===========================================================================
#define KST 68
#define VST 72
#define PST 68
#define ATTN_SMEM ((64 * KST + 64 * VST + 128 * PST) * 4)   // 70656 B

__global__ __launch_bounds__(128) void attn_mma()
{
    extern __shared__ float sm[];
    float* Ks = sm;                       // [64][KST]
    float* Vs = sm + 64 * KST;            // [64][VST]
    float* Ps = sm + 64 * KST + 64 * VST; // [128][PST]: Q staging, then P

    const int bh   = blockIdx.y;
    const int q0   = blockIdx.x * 128;
    const int b    = bh >> 4;
    const int h    = bh & 15;
    const int tid  = threadIdx.x;
    const int warp = tid >> 5;
    const int lane = tid & 31;
    const int g    = lane >> 2;
    const int t    = lane & 3;
    const int wm   = warp * 32;

    const float* gq = g_q + (((size_t)bh) << 11) * HDq;
    const float* gk = g_k + (((size_t)bh) << 11) * HDq;
    const float* gv = g_v + (((size_t)bh) << 11) * HDq;

    const uint32_t uKs = s2u(Ks), uVs = s2u(Vs), uPs = s2u(Ps);

    // ---- Stage Q via cp.async (2048 float4, 16 per thread) ----
    #pragma unroll
    for (int m = 0; m < 16; m++) {
        int idx = m * 128 + tid;
        int r = idx >> 4, c = (idx & 15) * 4;
        cp16(uPs + (r * PST + c) * 4, gq + (size_t)(q0 + r) * HDq + c);
    }
    CP_COMMIT(); CP_WAIT0();
    __syncthreads();

    // Build Q fragments (x 0.125 — exact, preserves tf32)
    unsigned qa[2][8][4];
    #pragma unroll
    for (int i = 0; i < 2; i++)
        #pragma unroll
        for (int k = 0; k < 8; k++) {
            const float* r0 = Ps + (wm + i * 16 + g) * PST + k * 8;
            const float* r1 = r0 + 8 * PST;
            qa[i][k][0] = __float_as_uint(r0[t] * 0.125f);
            qa[i][k][1] = __float_as_uint(r1[t] * 0.125f);
            qa[i][k][2] = __float_as_uint(r0[t + 4] * 0.125f);
            qa[i][k][3] = __float_as_uint(r1[t + 4] * 0.125f);
        }
    __syncthreads();

    float oacc[2][8][4] = {};
    float mrow[2][2] = { {-1e30f, -1e30f}, {-1e30f, -1e30f} };
    float lrow[2][2] = { {0.f, 0.f}, {0.f, 0.f} };

    for (int tile = 0; tile < Sq / 64; tile++) {
        // ---- Stage K and V via cp.async (1024 float4 each, 8/thread) ----
        #pragma unroll
        for (int m = 0; m < 8; m++) {
            int idx = m * 128 + tid;
            int r = idx >> 4, c = (idx & 15) * 4;
            const float* srcK = gk + (size_t)(tile * 64 + r) * HDq + c;
            const float* srcV = gv + (size_t)(tile * 64 + r) * HDq + c;
            cp16(uKs + (r * KST + c) * 4, srcK);
            cp16(uVs + (r * VST + c) * 4, srcV);
        }
        CP_COMMIT(); CP_WAIT0();
        __syncthreads();

        // ---- S = Q K^T ----
        float sacc[2][8][4] = {};
        #pragma unroll
        for (int k = 0; k < 8; k++) {
            #pragma unroll
            for (int j = 0; j < 8; j++) {
                const float* br = Ks + (j * 8 + g) * KST + k * 8;
                unsigned bf[2] = { __float_as_uint(br[t]),
                                   __float_as_uint(br[t + 4]) };
                mma_tf32(sacc[0][j], qa[0][k], bf);
                mma_tf32(sacc[1][j], qa[1][k], bf);
            }
        }

        // ---- Online softmax ----
        #pragma unroll
        for (int i = 0; i < 2; i++) {
            float mx0 = -1e30f, mx1 = -1e30f;
            #pragma unroll
            for (int j = 0; j < 8; j++) {
                mx0 = fmaxf(mx0, fmaxf(sacc[i][j][0], sacc[i][j][1]));
                mx1 = fmaxf(mx1, fmaxf(sacc[i][j][2], sacc[i][j][3]));
            }
            mx0 = fmaxf(mx0, __shfl_xor_sync(0xffffffffu, mx0, 1));
            mx0 = fmaxf(mx0, __shfl_xor_sync(0xffffffffu, mx0, 2));
            mx1 = fmaxf(mx1, __shfl_xor_sync(0xffffffffu, mx1, 1));
            mx1 = fmaxf(mx1, __shfl_xor_sync(0xffffffffu, mx1, 2));

            float nm0 = fmaxf(mrow[i][0], mx0), nm1 = fmaxf(mrow[i][1], mx1);
            float a0 = __expf(mrow[i][0] - nm0), a1 = __expf(mrow[i][1] - nm1);
            mrow[i][0] = nm0; mrow[i][1] = nm1;

            float ps0 = 0.f, ps1 = 0.f;
            #pragma unroll
            for (int j = 0; j < 8; j++) {
                sacc[i][j][0] = __expf(sacc[i][j][0] - nm0);
                sacc[i][j][1] = __expf(sacc[i][j][1] - nm0);
                sacc[i][j][2] = __expf(sacc[i][j][2] - nm1);
                sacc[i][j][3] = __expf(sacc[i][j][3] - nm1);
                ps0 += sacc[i][j][0] + sacc[i][j][1];
                ps1 += sacc[i][j][2] + sacc[i][j][3];
            }
            ps0 += __shfl_xor_sync(0xffffffffu, ps0, 1);
            ps0 += __shfl_xor_sync(0xffffffffu, ps0, 2);
            ps1 += __shfl_xor_sync(0xffffffffu, ps1, 1);
            ps1 += __shfl_xor_sync(0xffffffffu, ps1, 2);
            lrow[i][0] = lrow[i][0] * a0 + ps0;
            lrow[i][1] = lrow[i][1] * a1 + ps1;

            #pragma unroll
            for (int j = 0; j < 8; j++) {
                oacc[i][j][0] *= a0; oacc[i][j][1] *= a0;
                oacc[i][j][2] *= a1; oacc[i][j][3] *= a1;
            }
        }

        // ---- Store P (tf32) into Ps, interleaved pairs (warp-private) ----
        #pragma unroll
        for (int i = 0; i < 2; i++)
            #pragma unroll
            for (int j = 0; j < 8; j++) {
                *(float2*)(Ps + (wm + i * 16 + g) * PST + j * 8 + 2 * t) =
                    make_float2(tf32r(sacc[i][j][0]), tf32r(sacc[i][j][1]));
                *(float2*)(Ps + (wm + i * 16 + g + 8) * PST + j * 8 + 2 * t) =
                    make_float2(tf32r(sacc[i][j][2]), tf32r(sacc[i][j][3]));
            }
        __syncwarp();

        // ---- O += P V ----
        #pragma unroll
        for (int k = 0; k < 8; k++) {
            unsigned pa[2][4];
            #pragma unroll
            for (int i = 0; i < 2; i++) {
                const float* pr0 = Ps + (wm + i * 16 + g) * PST + k * 8;
                const float* pr1 = pr0 + 8 * PST;
                pa[i][0] = __float_as_uint(pr0[t]);
                pa[i][1] = __float_as_uint(pr1[t]);
                pa[i][2] = __float_as_uint(pr0[t + 4]);
                pa[i][3] = __float_as_uint(pr1[t + 4]);
            }
            #pragma unroll
            for (int j = 0; j < 8; j++) {
                unsigned bf[2] = {
                    __float_as_uint(Vs[(k * 8 + t) * VST + j * 8 + g]),
                    __float_as_uint(Vs[(k * 8 + t + 4) * VST + j * 8 + g]) };
                mma_tf32(oacc[0][j], pa[0], bf);
                mma_tf32(oacc[1][j], pa[1], bf);
            }
        }
        __syncthreads();
    }

    // ---- Epilogue: write tf32-rounded O / l ----
    #pragma unroll
    for (int i = 0; i < 2; i++) {
        float il0 = 1.0f / lrow[i][0], il1 = 1.0f / lrow[i][1];
        #pragma unroll
        for (int j = 0; j < 8; j++) {
            int r = q0 + wm + i * 16 + g;
            int col = h * HDq + j * 8 + 2 * t;
            size_t a0 = (size_t)(b * Sq + r) * Dq + col;
            size_t a1 = (size_t)(b * Sq + r + 8) * Dq + col;
            *(float2*)(g_att + a0) = make_float2(tf32r(oacc[i][j][0] * il0),
                                                 tf32r(oacc[i][j][1] * il0));
            *(float2*)(g_att + a1) = make_float2(tf32r(oacc[i][j][2] * il1),
                                                 tf32r(oacc[i][j][3] * il1));
        }
    }
}

// ---------------------------------------------------------------------------
// Launch.  Input order: xq, xv, xk, Wq, bq, Wk, bk, Wv, bv, Wo, bo
// ---------------------------------------------------------------------------
extern "C" void kernel_launch(void* const* d_in, const int* in_sizes, int n_in,
                              void* d_out, int out_size)
{
    const float* xq = (const float*)d_in[0];
    const float* xv = (const float*)d_in[1];
    const float* xk = (const float*)d_in[2];
    const float* Wq = (const float*)d_in[3];
    const float* bq = (const float*)d_in[4];
    const float* Wk = (const float*)d_in[5];
    const float* bk = (const float*)d_in[6];
    const float* Wv = (const float*)d_in[7];
    const float* bv = (const float*)d_in[8];
    const float* Wo = (const float*)d_in[9];
    const float* bo = (const float*)d_in[10];
    float* out = (float*)d_out;

    float *pq, *pk, *pv, *patt, *prx, *prw;
    cudaGetSymbolAddress((void**)&pq, g_q);
    cudaGetSymbolAddress((void**)&pk, g_k);
    cudaGetSymbolAddress((void**)&pv, g_v);
    cudaGetSymbolAddress((void**)&patt, g_att);
    cudaGetSymbolAddress((void**)&prx, g_rx);
    cudaGetSymbolAddress((void**)&prw, g_rw);

    static int attr_done = 0;
    if (!attr_done) {
        cudaFuncSetAttribute(gemm_cp,
            cudaFuncAttributeMaxDynamicSharedMemorySize, GEMM_SMEM);
        cudaFuncSetAttribute(attn_mma,
            cudaFuncAttributeMaxDynamicSharedMemorySize, ATTN_SMEM);
        attr_done = 1;
    }

    // Pre-round inputs and weights to tf32
    dim3 ground(1024, 7);
    round_tf32<<<ground, 256>>>(xq, xk, xv, Wq, Wk, Wv, Wo);

    const float* rxq = prx + 0 * (size_t)Mq * Dq;
    const float* rxk = prx + 1 * (size_t)Mq * Dq;
    const float* rxv = prx + 2 * (size_t)Mq * Dq;
    const float* rwq = prw + 0 * (size_t)Dq * Dq;
    const float* rwk = prw + 1 * (size_t)Dq * Dq;
    const float* rwv = prw + 2 * (size_t)Dq * Dq;
    const float* rwo = prw + 3 * (size_t)Dq * Dq;

    // Fused Q/K/V projections
    dim3 gqkv(Dq / 128, Mq / 128, 3);     // (8, 32, 3)
    gemm_cp<<<gqkv, 256, GEMM_SMEM>>>(
        rxq, rwq, bq, pq,
        rxk, rwk, bk, pk,
        rxv, rwv, bv, pv, 1);

    dim3 gattn(Sq / 128, Bq * Hq);        // (16, 32)
    attn_mma<<<gattn, 128, ATTN_SMEM>>>();

    // Output projection
    dim3 gproj(Dq / 128, Mq / 128, 1);    // (8, 32)
    gemm_cp<<<gproj, 256, GEMM_SMEM>>>(
        patt, rwo, bo, out,
        patt, rwo, bo, out,
        patt, rwo, bo, out, 0);
}

// round 11
// speedup vs baseline: 2.0493x; 1.0583x over previous
#include <cuda_runtime.h>
#include <cstdint>

// Problem constants
#define Bq 2
#define Sq 2048
#define Dq 1024
#define Hq 16
#define HDq 64
#define Mq (Bq * Sq)   // 4096
#define GK Dq          // 1024

// Scratch (device globals: allocation-free)
__device__ float g_q[Bq * Hq * Sq * HDq];    // [b][h][s][hd] (tf32-rounded)
__device__ float g_k[Bq * Hq * Sq * HDq];
__device__ float g_v[Bq * Hq * Sq * HDq];
__device__ float g_att[Mq * Dq];             // [b*s][d]      (tf32-rounded)
__device__ float g_rx[3][Mq * Dq];           // rounded xq, xk, xv
__device__ float g_rw[4][Dq * Dq];           // rounded Wq, Wk, Wv, Wo

// ---------------------------------------------------------------------------
// Helpers
// ---------------------------------------------------------------------------
__device__ __forceinline__ float tf32r(float x) {
    unsigned u;
    asm("cvt.rna.tf32.f32 %0, %1;" : "=r"(u) : "f"(x));
    return __uint_as_float(u);
}

__device__ __forceinline__ void mma_tf32(float c[4], const unsigned a[4],
                                         const unsigned b[2]) {
    asm volatile(
        "mma.sync.aligned.m16n8k8.row.col.f32.tf32.tf32.f32 "
        "{%0,%1,%2,%3}, {%4,%5,%6,%7}, {%8,%9}, {%0,%1,%2,%3};\n"
        : "+f"(c[0]), "+f"(c[1]), "+f"(c[2]), "+f"(c[3])
        : "r"(a[0]), "r"(a[1]), "r"(a[2]), "r"(a[3]),
          "r"(b[0]), "r"(b[1]));
}

__device__ __forceinline__ uint32_t s2u(const void* p) {
    uint32_t a;
    asm("{ .reg .u64 t; cvta.to.shared.u64 t, %1; cvt.u32.u64 %0, t; }"
        : "=r"(a) : "l"(p));
    return a;
}

__device__ __forceinline__ void cp16(uint32_t dst, const void* src) {
    asm volatile("cp.async.cg.shared.global [%0], [%1], 16;"
                 :: "r"(dst), "l"(src) : "memory");
}
#define CP_COMMIT() asm volatile("cp.async.commit_group;" ::: "memory")
#define CP_WAIT0()  asm volatile("cp.async.wait_group 0;" ::: "memory")
#define CP_WAIT1()  asm volatile("cp.async.wait_group 1;" ::: "memory")

// ---------------------------------------------------------------------------
// Pre-round inputs/weights to tf32 (rna) once per launch.
// ---------------------------------------------------------------------------
__global__ __launch_bounds__(256) void round_tf32(
    const float* xq, const float* xk, const float* xv,
    const float* wq, const float* wk, const float* wv, const float* wo)
{
    const float* src; float* dst; int n4;
    switch (blockIdx.y) {
        case 0: src = xq; dst = g_rx[0]; n4 = Mq * Dq / 4; break;
        case 1: src = xk; dst = g_rx[1]; n4 = Mq * Dq / 4; break;
        case 2: src = xv; dst = g_rx[2]; n4 = Mq * Dq / 4; break;
        case 3: src = wq; dst = g_rw[0]; n4 = Dq * Dq / 4; break;
        case 4: src = wk; dst = g_rw[1]; n4 = Dq * Dq / 4; break;
        case 5: src = wv; dst = g_rw[2]; n4 = Dq * Dq / 4; break;
        default: src = wo; dst = g_rw[3]; n4 = Dq * Dq / 4; break;
    }
    for (int i = blockIdx.x * 256 + threadIdx.x; i < n4; i += gridDim.x * 256) {
        float4 v = ((const float4*)src)[i];
        ((float4*)dst)[i] = make_float4(tf32r(v.x), tf32r(v.y),
                                        tf32r(v.z), tf32r(v.w));
    }
}

// ===========================================================================
// TF32 GEMM, NT (unchanged from R10): BM=BN=128, BK=32, 256 threads,
// 8 warps (4m x 2n), warp tile 32x64, 3-stage cp.async pipeline.
// ===========================================================================
#define GST 36
#define GSTAGE 3
#define GEMM_SMEM (GSTAGE * 2 * 128 * GST * 4)   // 110592 B

__global__ __launch_bounds__(256) void gemm_cp(
    const float* A0, const float* W0, const float* B0, float* C0,
    const float* A1, const float* W1, const float* B1, float* C1,
    const float* A2, const float* W2, const float* B2, float* C2,
    int head_major)
{
    extern __shared__ float sm[];
    const float* A; const float* W; const float* bias; float* C;
    if (blockIdx.z == 0)      { A = A0; W = W0; bias = B0; C = C0; }
    else if (blockIdx.z == 1) { A = A1; W = W1; bias = B1; C = C1; }
    else                      { A = A2; W = W2; bias = B2; C = C2; }

    const int tid  = threadIdx.x;
    const int warp = tid >> 5;
    const int lane = tid & 31;
    const int g    = lane >> 2;
    const int t    = lane & 3;
    const int wm   = (warp >> 1) * 32;
    const int wn   = (warp & 1) * 64;
    const int m0   = blockIdx.y * 128;
    const int n0   = blockIdx.x * 128;

    const uint32_t smu = s2u(sm);
    const float* pa = A + (size_t)m0 * GK;
    const float* pw = W + (size_t)n0 * GK;
    const int cr = tid >> 3;
    const int cc = (tid & 7) * 4;

    float acc[2][8][4] = {};

    #define STAGE(it_, buf_)                                                   \
    do {                                                                       \
        const int kk = (it_) * 32;                                             \
        const uint32_t sa = smu + (uint32_t)(buf_) * (2 * 128 * GST * 4);      \
        const uint32_t sw = sa + 128 * GST * 4;                                \
        _Pragma("unroll")                                                      \
        for (int q = 0; q < 4; q++) {                                          \
            int r = cr + q * 32;                                               \
            cp16(sa + (r * GST + cc) * 4, pa + (size_t)r * GK + kk + cc);      \
            cp16(sw + (r * GST + cc) * 4, pw + (size_t)r * GK + kk + cc);      \
        }                                                                      \
    } while (0)

    STAGE(0, 0); CP_COMMIT();
    STAGE(1, 1); CP_COMMIT();

    for (int it = 0; it < 32; it++) {
        CP_WAIT1();
        __syncthreads();
        if (it + 2 < 32) STAGE(it + 2, (it + 2) % 3);
        CP_COMMIT();

        const float* As = sm + (it % 3) * (2 * 128 * GST);
        const float* Ws = As + 128 * GST;
        #pragma unroll
        for (int ks = 0; ks < 4; ks++) {
            const int kc = ks * 8 + t;
            unsigned af[2][4];
            #pragma unroll
            for (int i = 0; i < 2; i++) {
                const float* ar = As + (wm + i * 16 + g) * GST;
                af[i][0] = __float_as_uint(ar[kc]);
                af[i][1] = __float_as_uint(ar[8 * GST + kc]);
                af[i][2] = __float_as_uint(ar[kc + 4]);
                af[i][3] = __float_as_uint(ar[8 * GST + kc + 4]);
            }
            #pragma unroll
            for (int j = 0; j < 8; j++) {
                const float* br = Ws + (wn + j * 8 + g) * GST;
                unsigned bf[2] = { __float_as_uint(br[kc]),
                                   __float_as_uint(br[kc + 4]) };
                mma_tf32(acc[0][j], af[0], bf);
                mma_tf32(acc[1][j], af[1], bf);
            }
        }
    }
    #undef STAGE

    #pragma unroll
    for (int i = 0; i < 2; i++) {
        #pragma unroll
        for (int j = 0; j < 8; j++) {
            int mrow = m0 + wm + i * 16 + g;
            int ncol = n0 + wn + j * 8 + t * 2;
            float b0 = bias[ncol], b1 = bias[ncol + 1];
            float2 lo = make_float2(acc[i][j][0] + b0, acc[i][j][1] + b1);
            float2 hi = make_float2(acc[i][j][2] + b0, acc[i][j][3] + b1);
            if (head_major) {
                lo = make_float2(tf32r(lo.x), tf32r(lo.y));
                hi = make_float2(tf32r(hi.x), tf32r(hi.y));
                int hh = ncol >> 6, hd = ncol & 63;
                size_t a0 = ((((size_t)(mrow >> 11) * Hq + hh) << 11)
                             + (mrow & 2047)) * HDq + hd;
                int mr2 = mrow + 8;
                size_t a1 = ((((size_t)(mr2 >> 11) * Hq + hh) << 11)
                             + (mr2 & 2047)) * HDq + hd;
                *(float2*)(C + a0) = lo;
                *(float2*)(C + a1) = hi;
            } else {
                *(float2*)(C + (size_t)mrow * GK + ncol) = lo;
                *(float2*)(C + (size_t)(mrow + 8) * GK + ncol) = hi;
            }
        }
    }
}

// ===========================================================================
// TF32 flash attention: 128 queries/block, 4 warps x 32 rows (2 x m16),
// 64-key tiles. DOUBLE-BUFFERED cp.async K/V staging: tile t+1 issued at
// the top of iteration t (WAR-safe via end-of-iter barrier), wait_group 1.
// K stride 68, V stride 72, P stride 68 — all conflict-free.
// ===========================================================================
#define KST 68
#define VST 72
#define PST 68
#define AKV (64 * KST + 64 * VST)              // floats per stage
#define ATTN_SMEM ((2 * AKV + 128 * PST) * 4)  // 106496 B

__global__ __launch_bounds__(128) void attn_mma()
{
    extern __shared__ float sm[];
    float* Ps = sm + 2 * AKV;             // [128][PST]: Q staging, then P

    const int bh   = blockIdx.y;
    const int q0   = blockIdx.x * 128;
    const int b    = bh >> 4;
    const int h    = bh & 15;
    const int tid  = threadIdx.x;
    const int warp = tid >> 5;
    const int lane = tid & 31;
    const int g    = lane >> 2;
    const int t    = lane & 3;
    const int wm   = warp * 32;

    const float* gq = g_q + (((size_t)bh) << 11) * HDq;
    const float* gk = g_k + (((size_t)bh) << 11) * HDq;
    const float* gv = g_v + (((size_t)bh) << 11) * HDq;

    const uint32_t smu = s2u(sm);
    const uint32_t uPs = s2u(Ps);

    // stage K/V tile `tl_` into buffer `bf_` (1024 float4 each, 8/thread)
    #define STAGE_KV(tl_, bf_)                                                 \
    do {                                                                       \
        const uint32_t sk = smu + (uint32_t)(bf_) * (AKV * 4);                 \
        const uint32_t sv = sk + 64 * KST * 4;                                 \
        _Pragma("unroll")                                                      \
        for (int m = 0; m < 8; m++) {                                          \
            int idx = m * 128 + tid;                                           \
            int r = idx >> 4, c = (idx & 15) * 4;                              \
            const float* bK = gk + (size_t)((tl_) * 64 + r) * HDq + c;         \
            const float* bV = gv + (size_t)((tl_) * 64 + r) * HDq + c;         \
            cp16(sk + (r * KST + c) * 4, bK);                                  \
            cp16(sv + (r * VST + c) * 4, bV);                                  \
        }                                                                      \
    } while (0)

    // ---- Stage Q (group A) and tile 0 K/V (group B) ----
    #pragma unroll
    for (int m = 0; m < 16; m++) {
        int idx = m * 128 + tid;
        int r = idx >> 4, c = (idx & 15) * 4;
        cp16(uPs + (r * PST + c) * 4, gq + (size_t)(q0 + r) * HDq + c);
    }
    CP_COMMIT();
    STAGE_KV(0, 0); CP_COMMIT();
    CP_WAIT1();                            // Q resident; tile 0 in flight
    __syncthreads();

    // Build Q fragments (x 0.125 — exact, preserves tf32)
    unsigned qa[2][8][4];
    #pragma unroll
    for (int i = 0; i < 2; i++)
        #pragma unroll
        for (int k = 0; k < 8; k++) {
            const float* r0 = Ps + (wm + i * 16 + g) * PST + k * 8;
            const float* r1 = r0 + 8 * PST;
            qa[i][k][0] = __float_as_uint(r0[t] * 0.125f);
            qa[i][k][1] = __float_as_uint(r1[t] * 0.125f);
            qa[i][k][2] = __float_as_uint(r0[t + 4] * 0.125f);
            qa[i][k][3] = __float_as_uint(r1[t + 4] * 0.125f);
        }
    __syncthreads();

    float oacc[2][8][4] = {};
    float mrow[2][2] = { {-1e30f, -1e30f}, {-1e30f, -1e30f} };
    float lrow[2][2] = { {0.f, 0.f}, {0.f, 0.f} };

    for (int tile = 0; tile < Sq / 64; tile++) {
        // ---- Prefetch tile+1 into the alternate buffer, wait for tile ----
        if (tile + 1 < Sq / 64) {
            STAGE_KV(tile + 1, (tile + 1) & 1);
            CP_COMMIT();
            CP_WAIT1();
        } else {
            CP_WAIT0();
        }
        __syncthreads();

        const float* Ks = sm + (tile & 1) * AKV;
        const float* Vs = Ks + 64 * KST;

        // ---- S = Q K^T ----
        float sacc[2][8][4] = {};
        #pragma unroll
        for (int k = 0; k < 8; k++) {
            #pragma unroll
            for (int j = 0; j < 8; j++) {
                const float* br = Ks + (j * 8 + g) * KST + k * 8;
                unsigned bf[2] = { __float_as_uint(br[t]),
                                   __float_as_uint(br[t + 4]) };
                mma_tf32(sacc[0][j], qa[0][k], bf);
                mma_tf32(sacc[1][j], qa[1][k], bf);
            }
        }

        // ---- Online softmax ----
        #pragma unroll
        for (int i = 0; i < 2; i++) {
            float mx0 = -1e30f, mx1 = -1e30f;
            #pragma unroll
            for (int j = 0; j < 8; j++) {
                mx0 = fmaxf(mx0, fmaxf(sacc[i][j][0], sacc[i][j][1]));
                mx1 = fmaxf(mx1, fmaxf(sacc[i][j][2], sacc[i][j][3]));
            }
            mx0 = fmaxf(mx0, __shfl_xor_sync(0xffffffffu, mx0, 1));
            mx0 = fmaxf(mx0, __shfl_xor_sync(0xffffffffu, mx0, 2));
            mx1 = fmaxf(mx1, __shfl_xor_sync(0xffffffffu, mx1, 1));
            mx1 = fmaxf(mx1, __shfl_xor_sync(0xffffffffu, mx1, 2));

            float nm0 = fmaxf(mrow[i][0], mx0), nm1 = fmaxf(mrow[i][1], mx1);
            float a0 = __expf(mrow[i][0] - nm0), a1 = __expf(mrow[i][1] - nm1);
            mrow[i][0] = nm0; mrow[i][1] = nm1;

            float ps0 = 0.f, ps1 = 0.f;
            #pragma unroll
            for (int j = 0; j < 8; j++) {
                sacc[i][j][0] = __expf(sacc[i][j][0] - nm0);
                sacc[i][j][1] = __expf(sacc[i][j][1] - nm0);
                sacc[i][j][2] = __expf(sacc[i][j][2] - nm1);
                sacc[i][j][3] = __expf(sacc[i][j][3] - nm1);
                ps0 += sacc[i][j][0] + sacc[i][j][1];
                ps1 += sacc[i][j][2] + sacc[i][j][3];
            }
            ps0 += __shfl_xor_sync(0xffffffffu, ps0, 1);
            ps0 += __shfl_xor_sync(0xffffffffu, ps0, 2);
            ps1 += __shfl_xor_sync(0xffffffffu, ps1, 1);
            ps1 += __shfl_xor_sync(0xffffffffu, ps1, 2);
            lrow[i][0] = lrow[i][0] * a0 + ps0;
            lrow[i][1] = lrow[i][1] * a1 + ps1;

            #pragma unroll
            for (int j = 0; j < 8; j++) {
                oacc[i][j][0] *= a0; oacc[i][j][1] *= a0;
                oacc[i][j][2] *= a1; oacc[i][j][3] *= a1;
            }
        }

        // ---- Store P (tf32) into Ps (warp-private rows) ----
        #pragma unroll
        for (int i = 0; i < 2; i++)
            #pragma unroll
            for (int j = 0; j < 8; j++) {
                *(float2*)(Ps + (wm + i * 16 + g) * PST + j * 8 + 2 * t) =
                    make_float2(tf32r(sacc[i][j][0]), tf32r(sacc[i][j][1]));
                *(float2*)(Ps + (wm + i * 16 + g + 8) * PST + j * 8 + 2 * t) =
                    make_float2(tf32r(sacc[i][j][2]), tf32r(sacc[i][j][3]));
            }
        __syncwarp();

        // ---- O += P V ----
        #pragma unroll
        for (int k = 0; k < 8; k++) {
            unsigned pa[2][4];
            #pragma unroll
            for (int i = 0; i < 2; i++) {
                const float* pr0 = Ps + (wm + i * 16 + g) * PST + k * 8;
                const float* pr1 = pr0 + 8 * PST;
                pa[i][0] = __float_as_uint(pr0[t]);
                pa[i][1] = __float_as_uint(pr1[t]);
                pa[i][2] = __float_as_uint(pr0[t + 4]);
                pa[i][3] = __float_as_uint(pr1[t + 4]);
            }
            #pragma unroll
            for (int j = 0; j < 8; j++) {
                unsigned bf[2] = {
                    __float_as_uint(Vs[(k * 8 + t) * VST + j * 8 + g]),
                    __float_as_uint(Vs[(k * 8 + t + 4) * VST + j * 8 + g]) };
                mma_tf32(oacc[0][j], pa[0], bf);
                mma_tf32(oacc[1][j], pa[1], bf);
            }
        }
        __syncthreads();   // closes reads of buf (tile&1) and Ps for this iter
    }
    #undef STAGE_KV

    // ---- Epilogue: write tf32-rounded O / l ----
    #pragma unroll
    for (int i = 0; i < 2; i++) {
        float il0 = 1.0f / lrow[i][0], il1 = 1.0f / lrow[i][1];
        #pragma unroll
        for (int j = 0; j < 8; j++) {
            int r = q0 + wm + i * 16 + g;
            int col = h * HDq + j * 8 + 2 * t;
            size_t a0 = (size_t)(b * Sq + r) * Dq + col;
            size_t a1 = (size_t)(b * Sq + r + 8) * Dq + col;
            *(float2*)(g_att + a0) = make_float2(tf32r(oacc[i][j][0] * il0),
                                                 tf32r(oacc[i][j][1] * il0));
            *(float2*)(g_att + a1) = make_float2(tf32r(oacc[i][j][2] * il1),
                                                 tf32r(oacc[i][j][3] * il1));
        }
    }
}

// ---------------------------------------------------------------------------
// Launch.  Input order: xq, xv, xk, Wq, bq, Wk, bk, Wv, bv, Wo, bo
// ---------------------------------------------------------------------------
extern "C" void kernel_launch(void* const* d_in, const int* in_sizes, int n_in,
                              void* d_out, int out_size)
{
    const float* xq = (const float*)d_in[0];
    const float* xv = (const float*)d_in[1];
    const float* xk = (const float*)d_in[2];
    const float* Wq = (const float*)d_in[3];
    const float* bq = (const float*)d_in[4];
    const float* Wk = (const float*)d_in[5];
    const float* bk = (const float*)d_in[6];
    const float* Wv = (const float*)d_in[7];
    const float* bv = (const float*)d_in[8];
    const float* Wo = (const float*)d_in[9];
    const float* bo = (const float*)d_in[10];
    float* out = (float*)d_out;

    float *pq, *pk, *pv, *patt, *prx, *prw;
    cudaGetSymbolAddress((void**)&pq, g_q);
    cudaGetSymbolAddress((void**)&pk, g_k);
    cudaGetSymbolAddress((void**)&pv, g_v);
    cudaGetSymbolAddress((void**)&patt, g_att);
    cudaGetSymbolAddress((void**)&prx, g_rx);
    cudaGetSymbolAddress((void**)&prw, g_rw);

    static int attr_done = 0;
    if (!attr_done) {
        cudaFuncSetAttribute(gemm_cp,
            cudaFuncAttributeMaxDynamicSharedMemorySize, GEMM_SMEM);
        cudaFuncSetAttribute(attn_mma,
            cudaFuncAttributeMaxDynamicSharedMemorySize, ATTN_SMEM);
        attr_done = 1;
    }

    // Pre-round inputs and weights to tf32
    dim3 ground(1024, 7);
    round_tf32<<<ground, 256>>>(xq, xk, xv, Wq, Wk, Wv, Wo);

    const float* rxq = prx + 0 * (size_t)Mq * Dq;
    const float* rxk = prx + 1 * (size_t)Mq * Dq;
    const float* rxv = prx + 2 * (size_t)Mq * Dq;
    const float* rwq = prw + 0 * (size_t)Dq * Dq;
    const float* rwk = prw + 1 * (size_t)Dq * Dq;
    const float* rwv = prw + 2 * (size_t)Dq * Dq;
    const float* rwo = prw + 3 * (size_t)Dq * Dq;

    // Fused Q/K/V projections
    dim3 gqkv(Dq / 128, Mq / 128, 3);     // (8, 32, 3)
    gemm_cp<<<gqkv, 256, GEMM_SMEM>>>(
        rxq, rwq, bq, pq,
        rxk, rwk, bk, pk,
        rxv, rwv, bv, pv, 1);

    dim3 gattn(Sq / 128, Bq * Hq);        // (16, 32)
    attn_mma<<<gattn, 128, ATTN_SMEM>>>();

    // Output projection
    dim3 gproj(Dq / 128, Mq / 128, 1);    // (8, 32)
    gemm_cp<<<gproj, 256, GEMM_SMEM>>>(
        patt, rwo, bo, out,
        patt, rwo, bo, out,
        patt, rwo, bo, out, 0);
}

// round 12
// speedup vs baseline: 2.0807x; 1.0153x over previous
#include <cuda_runtime.h>
#include <cstdint>

// Problem constants
#define Bq 2
#define Sq 2048
#define Dq 1024
#define Hq 16
#define HDq 64
#define Mq (Bq * Sq)   // 4096
#define GK Dq          // 1024

// Interleaved column permutation within each 8-col k-group:
// logical col u -> position ((u&3)*2) | (u>>2)  (pairs (t, t+4) adjacent)
__device__ __forceinline__ int perm8(int u) { return ((u & 3) << 1) | (u >> 2); }

// Scratch (device globals: allocation-free). All *interleaved* tf32 layouts.
__device__ float g_q[Bq * Hq * Sq * HDq];    // [b][h][s][hd-perm]
__device__ float g_k[Bq * Hq * Sq * HDq];
__device__ float g_v[Bq * Hq * Sq * HDq];
__device__ float g_att[Mq * Dq];             // [b*s][d-perm]
__device__ float g_rx[3][Mq * Dq];           // perm-rounded xq, xk, xv
__device__ float g_rw[4][Dq * Dq];           // perm-rounded Wq, Wk, Wv, Wo

// ---------------------------------------------------------------------------
// Helpers
// ---------------------------------------------------------------------------
__device__ __forceinline__ float tf32r(float x) {
    unsigned u;
    asm("cvt.rna.tf32.f32 %0, %1;" : "=r"(u) : "f"(x));
    return __uint_as_float(u);
}

__device__ __forceinline__ void mma_tf32(float c[4], const unsigned a[4],
                                         const unsigned b[2]) {
    asm volatile(
        "mma.sync.aligned.m16n8k8.row.col.f32.tf32.tf32.f32 "
        "{%0,%1,%2,%3}, {%4,%5,%6,%7}, {%8,%9}, {%0,%1,%2,%3};\n"
        : "+f"(c[0]), "+f"(c[1]), "+f"(c[2]), "+f"(c[3])
        : "r"(a[0]), "r"(a[1]), "r"(a[2]), "r"(a[3]),
          "r"(b[0]), "r"(b[1]));
}

__device__ __forceinline__ uint32_t s2u(const void* p) {
    uint32_t a;
    asm("{ .reg .u64 t; cvta.to.shared.u64 t, %1; cvt.u32.u64 %0, t; }"
        : "=r"(a) : "l"(p));
    return a;
}

__device__ __forceinline__ void cp16(uint32_t dst, const void* src) {
    asm volatile("cp.async.cg.shared.global [%0], [%1], 16;"
                 :: "r"(dst), "l"(src) : "memory");
}
#define CP_COMMIT() asm volatile("cp.async.commit_group;" ::: "memory")
#define CP_WAIT0()  asm volatile("cp.async.wait_group 0;" ::: "memory")
#define CP_WAIT1()  asm volatile("cp.async.wait_group 1;" ::: "memory")

// ---------------------------------------------------------------------------
// Pre-round + column-interleave inputs/weights to tf32 (rna), once per launch.
// Each thread handles whole 8-col groups: out = (x0,x4,x1,x5),(x2,x6,x3,x7).
// ---------------------------------------------------------------------------
__global__ __launch_bounds__(256) void round_tf32(
    const float* xq, const float* xk, const float* xv,
    const float* wq, const float* wk, const float* wv, const float* wo)
{
    const float* src; float* dst; int n8;
    switch (blockIdx.y) {
        case 0: src = xq; dst = g_rx[0]; n8 = Mq * Dq / 8; break;
        case 1: src = xk; dst = g_rx[1]; n8 = Mq * Dq / 8; break;
        case 2: src = xv; dst = g_rx[2]; n8 = Mq * Dq / 8; break;
        case 3: src = wq; dst = g_rw[0]; n8 = Dq * Dq / 8; break;
        case 4: src = wk; dst = g_rw[1]; n8 = Dq * Dq / 8; break;
        case 5: src = wv; dst = g_rw[2]; n8 = Dq * Dq / 8; break;
        default: src = wo; dst = g_rw[3]; n8 = Dq * Dq / 8; break;
    }
    for (int i = blockIdx.x * 256 + threadIdx.x; i < n8; i += gridDim.x * 256) {
        float4 v0 = ((const float4*)src)[2 * i];
        float4 v1 = ((const float4*)src)[2 * i + 1];
        ((float4*)dst)[2 * i]     = make_float4(tf32r(v0.x), tf32r(v1.x),
                                                tf32r(v0.y), tf32r(v1.y));
        ((float4*)dst)[2 * i + 1] = make_float4(tf32r(v0.z), tf32r(v1.z),
                                                tf32r(v0.w), tf32r(v1.w));
    }
}

// ===========================================================================
// TF32 GEMM, NT: C[m,n] = sum_k A[m,k]*W[n,k] + bias[n]
// A and W pre-rounded + interleaved. BM=BN=128, BK=32, 256 threads, 8 warps
// (4m x 2n), warp tile 32x64. 2-stage cp.async pipeline (80 KB -> 2 CTA/SM).
// Fragment loads are LDS.64 (pairs), stride 40 -> conflict-free (8g+2t).
// ===========================================================================
#define GST 40
#define GSTAGE 2
#define GEMM_SMEM (GSTAGE * 2 * 128 * GST * 4)   // 81920 B

__global__ __launch_bounds__(256) void gemm_cp(
    const float* A0, const float* W0, const float* B0, float* C0,
    const float* A1, const float* W1, const float* B1, float* C1,
    const float* A2, const float* W2, const float* B2, float* C2,
    int head_major)
{
    extern __shared__ float sm[];
    const float* A; const float* W; const float* bias; float* C;
    if (blockIdx.z == 0)      { A = A0; W = W0; bias = B0; C = C0; }
    else if (blockIdx.z == 1) { A = A1; W = W1; bias = B1; C = C1; }
    else                      { A = A2; W = W2; bias = B2; C = C2; }

    const int tid  = threadIdx.x;
    const int warp = tid >> 5;
    const int lane = tid & 31;
    const int g    = lane >> 2;
    const int t    = lane & 3;
    const int wm   = (warp >> 1) * 32;
    const int wn   = (warp & 1) * 64;
    const int m0   = blockIdx.y * 128;
    const int n0   = blockIdx.x * 128;

    const uint32_t smu = s2u(sm);
    const float* pa = A + (size_t)m0 * GK;
    const float* pw = W + (size_t)n0 * GK;
    const int cr = tid >> 3;
    const int cc = (tid & 7) * 4;

    float acc[2][8][4] = {};

    #define STAGE(it_, buf_)                                                   \
    do {                                                                       \
        const int kk = (it_) * 32;                                             \
        const uint32_t sa = smu + (uint32_t)(buf_) * (2 * 128 * GST * 4);      \
        const uint32_t sw = sa + 128 * GST * 4;                                \
        _Pragma("unroll")                                                      \
        for (int q = 0; q < 4; q++) {                                          \
            int r = cr + q * 32;                                               \
            cp16(sa + (r * GST + cc) * 4, pa + (size_t)r * GK + kk + cc);      \
            cp16(sw + (r * GST + cc) * 4, pw + (size_t)r * GK + kk + cc);      \
        }                                                                      \
    } while (0)

    STAGE(0, 0); CP_COMMIT();

    for (int it = 0; it < 32; it++) {
        __syncthreads();              // closes reads of buffer (it+1)&1
        if (it + 1 < 32) STAGE(it + 1, (it + 1) & 1);
        CP_COMMIT();
        CP_WAIT1();                   // stage `it` resident
        __syncthreads();

        const float* As = sm + (it & 1) * (2 * 128 * GST);
        const float* Ws = As + 128 * GST;
        #pragma unroll
        for (int ks = 0; ks < 4; ks++) {
            const int kc = ks * 8 + 2 * t;
            unsigned af[2][4];
            #pragma unroll
            for (int i = 0; i < 2; i++) {
                float2 p0 = *(const float2*)(As + (wm + i * 16 + g) * GST + kc);
                float2 p1 = *(const float2*)(As + (wm + i * 16 + g + 8) * GST + kc);
                af[i][0] = __float_as_uint(p0.x);
                af[i][1] = __float_as_uint(p1.x);
                af[i][2] = __float_as_uint(p0.y);
                af[i][3] = __float_as_uint(p1.y);
            }
            #pragma unroll
            for (int j = 0; j < 8; j++) {
                float2 pb = *(const float2*)(Ws + (wn + j * 8 + g) * GST + kc);
                unsigned bf[2] = { __float_as_uint(pb.x), __float_as_uint(pb.y) };
                mma_tf32(acc[0][j], af[0], bf);
                mma_tf32(acc[1][j], af[1], bf);
            }
        }
    }
    #undef STAGE

    // Epilogue. Logical cols c0 = 2t, c1 = 2t+1 within group j.
    const int p0c = perm8(2 * t);
    const int p1c = perm8(2 * t + 1);
    #pragma unroll
    for (int i = 0; i < 2; i++) {
        #pragma unroll
        for (int j = 0; j < 8; j++) {
            int mrow = m0 + wm + i * 16 + g;
            int ncol = n0 + wn + j * 8 + t * 2;
            float b0 = bias[ncol], b1 = bias[ncol + 1];
            float2 lo = make_float2(acc[i][j][0] + b0, acc[i][j][1] + b1);
            float2 hi = make_float2(acc[i][j][2] + b0, acc[i][j][3] + b1);
            if (head_major) {
                // write tf32-rounded, interleaved positions, [b][h][s][hd]
                int hh = ncol >> 6;
                int hdg = (ncol & 63) - 2 * t;      // group base in head dim
                size_t r0 = ((((size_t)(mrow >> 11) * Hq + hh) << 11)
                             + (mrow & 2047)) * HDq + hdg;
                int mr2 = mrow + 8;
                size_t r1 = ((((size_t)(mr2 >> 11) * Hq + hh) << 11)
                             + (mr2 & 2047)) * HDq + hdg;
                C[r0 + p0c] = tf32r(lo.x);
                C[r0 + p1c] = tf32r(lo.y);
                C[r1 + p0c] = tf32r(hi.x);
                C[r1 + p1c] = tf32r(hi.y);
            } else {
                *(float2*)(C + (size_t)mrow * GK + ncol) = lo;
                *(float2*)(C + (size_t)(mrow + 8) * GK + ncol) = hi;
            }
        }
    }
}

// ===========================================================================
// TF32 flash attention: 128 queries/block, 4 warps x 32 rows (2 x m16),
// 64-key tiles, double-buffered cp.async K/V. Q/K interleaved -> LDS.64
// fragment pairs (stride 72, conflict-free per half-warp). V indexed with
// permuted column pg. P phase plain (stride 68). Output g_att interleaved.
// ===========================================================================
#define KST 72
#define VST 72
#define PST 68
#define AKV (64 * KST + 64 * VST)              // floats per stage
#define ATTN_SMEM ((2 * AKV + 128 * PST) * 4)  // 108544 B

__global__ __launch_bounds__(128) void attn_mma()
{
    extern __shared__ float sm[];
    float* Ps = sm + 2 * AKV;             // [128][PST]: Q staging, then P

    const int bh   = blockIdx.y;
    const int q0   = blockIdx.x * 128;
    const int b    = bh >> 4;
    const int h    = bh & 15;
    const int tid  = threadIdx.x;
    const int warp = tid >> 5;
    const int lane = tid & 31;
    const int g    = lane >> 2;
    const int t    = lane & 3;
    const int wm   = warp * 32;
    const int pg   = perm8(g);            // permuted position of col g

    const float* gq = g_q + (((size_t)bh) << 11) * HDq;
    const float* gk = g_k + (((size_t)bh) << 11) * HDq;
    const float* gv = g_v + (((size_t)bh) << 11) * HDq;

    const uint32_t smu = s2u(sm);
    const uint32_t uPs = s2u(Ps);

    #define STAGE_KV(tl_, bf_)                                                 \
    do {                                                                       \
        const uint32_t sk = smu + (uint32_t)(bf_) * (AKV * 4);                 \
        const uint32_t sv = sk + 64 * KST * 4;                                 \
        _Pragma("unroll")                                                      \
        for (int m = 0; m < 8; m++) {                                          \
            int idx = m * 128 + tid;                                           \
            int r = idx >> 4, c = (idx & 15) * 4;                              \
            const float* bK = gk + (size_t)((tl_) * 64 + r) * HDq + c;         \
            const float* bV = gv + (size_t)((tl_) * 64 + r) * HDq + c;         \
            cp16(sk + (r * KST + c) * 4, bK);                                  \
            cp16(sv + (r * VST + c) * 4, bV);                                  \
        }                                                                      \
    } while (0)

    // ---- Stage Q (group A) and tile 0 K/V (group B) ----
    #pragma unroll
    for (int m = 0; m < 16; m++) {
        int idx = m * 128 + tid;
        int r = idx >> 4, c = (idx & 15) * 4;
        cp16(uPs + (r * PST + c) * 4, gq + (size_t)(q0 + r) * HDq + c);
    }
    CP_COMMIT();
    STAGE_KV(0, 0); CP_COMMIT();
    CP_WAIT1();
    __syncthreads();

    // Build Q fragments from interleaved pairs (x 0.125 exact)
    unsigned qa[2][8][4];
    #pragma unroll
    for (int i = 0; i < 2; i++)
        #pragma unroll
        for (int k = 0; k < 8; k++) {
            float2 p0 = *(const float2*)(Ps + (wm + i * 16 + g) * PST + k * 8 + 2 * t);
            float2 p1 = *(const float2*)(Ps + (wm + i * 16 + g + 8) * PST + k * 8 + 2 * t);
            qa[i][k][0] = __float_as_uint(p0.x * 0.125f);
            qa[i][k][1] = __float_as_uint(p1.x * 0.125f);
            qa[i][k][2] = __float_as_uint(p0.y * 0.125f);
            qa[i][k][3] = __float_as_uint(p1.y * 0.125f);
        }
    __syncthreads();

    float oacc[2][8][4] = {};
    float mrow[2][2] = { {-1e30f, -1e30f}, {-1e30f, -1e30f} };
    float lrow[2][2] = { {0.f, 0.f}, {0.f, 0.f} };

    for (int tile = 0; tile < Sq / 64; tile++) {
        if (tile + 1 < Sq / 64) {
            STAGE_KV(tile + 1, (tile + 1) & 1);
            CP_COMMIT();
            CP_WAIT1();
        } else {
            CP_WAIT0();
        }
        __syncthreads();

        const float* Ks = sm + (tile & 1) * AKV;
        const float* Vs = Ks + 64 * KST;

        // ---- S = Q K^T : B-frags as LDS.64 pairs ----
        float sacc[2][8][4] = {};
        #pragma unroll
        for (int k = 0; k < 8; k++) {
            #pragma unroll
            for (int j = 0; j < 8; j++) {
                float2 pb = *(const float2*)(Ks + (j * 8 + g) * KST + k * 8 + 2 * t);
                unsigned bf[2] = { __float_as_uint(pb.x), __float_as_uint(pb.y) };
                mma_tf32(sacc[0][j], qa[0][k], bf);
                mma_tf32(sacc[1][j], qa[1][k], bf);
            }
        }

        // ---- Online softmax ----
        #pragma unroll
        for (int i = 0; i < 2; i++) {
            float mx0 = -1e30f, mx1 = -1e30f;
            #pragma unroll
            for (int j = 0; j < 8; j++) {
                mx0 = fmaxf(mx0, fmaxf(sacc[i][j][0], sacc[i][j][1]));
                mx1 = fmaxf(mx1, fmaxf(sacc[i][j][2], sacc[i][j][3]));
            }
            mx0 = fmaxf(mx0, __shfl_xor_sync(0xffffffffu, mx0, 1));
            mx0 = fmaxf(mx0, __shfl_xor_sync(0xffffffffu, mx0, 2));
            mx1 = fmaxf(mx1, __shfl_xor_sync(0xffffffffu, mx1, 1));
            mx1 = fmaxf(mx1, __shfl_xor_sync(0xffffffffu, mx1, 2));

            float nm0 = fmaxf(mrow[i][0], mx0), nm1 = fmaxf(mrow[i][1], mx1);
            float a0 = __expf(mrow[i][0] - nm0), a1 = __expf(mrow[i][1] - nm1);
            mrow[i][0] = nm0; mrow[i][1] = nm1;

            float ps0 = 0.f, ps1 = 0.f;
            #pragma unroll
            for (int j = 0; j < 8; j++) {
                sacc[i][j][0] = __expf(sacc[i][j][0] - nm0);
                sacc[i][j][1] = __expf(sacc[i][j][1] - nm0);
                sacc[i][j][2] = __expf(sacc[i][j][2] - nm1);
                sacc[i][j][3] = __expf(sacc[i][j][3] - nm1);
                ps0 += sacc[i][j][0] + sacc[i][j][1];
                ps1 += sacc[i][j][2] + sacc[i][j][3];
            }
            ps0 += __shfl_xor_sync(0xffffffffu, ps0, 1);
            ps0 += __shfl_xor_sync(0xffffffffu, ps0, 2);
            ps1 += __shfl_xor_sync(0xffffffffu, ps1, 1);
            ps1 += __shfl_xor_sync(0xffffffffu, ps1, 2);
            lrow[i][0] = lrow[i][0] * a0 + ps0;
            lrow[i][1] = lrow[i][1] * a1 + ps1;

            #pragma unroll
            for (int j = 0; j < 8; j++) {
                oacc[i][j][0] *= a0; oacc[i][j][1] *= a0;
                oacc[i][j][2] *= a1; oacc[i][j][3] *= a1;
            }
        }

        // ---- Store P (tf32) into Ps, plain layout (warp-private rows) ----
        #pragma unroll
        for (int i = 0; i < 2; i++)
            #pragma unroll
            for (int j = 0; j < 8; j++) {
                *(float2*)(Ps + (wm + i * 16 + g) * PST + j * 8 + 2 * t) =
                    make_float2(tf32r(sacc[i][j][0]), tf32r(sacc[i][j][1]));
                *(float2*)(Ps + (wm + i * 16 + g + 8) * PST + j * 8 + 2 * t) =
                    make_float2(tf32r(sacc[i][j][2]), tf32r(sacc[i][j][3]));
            }
        __syncwarp();

        // ---- O += P V : V columns via permuted index pg ----
        #pragma unroll
        for (int k = 0; k < 8; k++) {
            unsigned pa[2][4];
            #pragma unroll
            for (int i = 0; i < 2; i++) {
                const float* pr0 = Ps + (wm + i * 16 + g) * PST + k * 8;
                const float* pr1 = pr0 + 8 * PST;
                pa[i][0] = __float_as_uint(pr0[t]);
                pa[i][1] = __float_as_uint(pr1[t]);
                pa[i][2] = __float_as_uint(pr0[t + 4]);
                pa[i][3] = __float_as_uint(pr1[t + 4]);
            }
            #pragma unroll
            for (int j = 0; j < 8; j++) {
                unsigned bf[2] = {
                    __float_as_uint(Vs[(k * 8 + t) * VST + j * 8 + pg]),
                    __float_as_uint(Vs[(k * 8 + t + 4) * VST + j * 8 + pg]) };
                mma_tf32(oacc[0][j], pa[0], bf);
                mma_tf32(oacc[1][j], pa[1], bf);
            }
        }
        __syncthreads();
    }
    #undef STAGE_KV

    // ---- Epilogue: tf32-rounded O / l, interleaved positions ----
    const int p0c = perm8(2 * t);
    const int p1c = perm8(2 * t + 1);
    #pragma unroll
    for (int i = 0; i < 2; i++) {
        float il0 = 1.0f / lrow[i][0], il1 = 1.0f / lrow[i][1];
        #pragma unroll
        for (int j = 0; j < 8; j++) {
            int r = q0 + wm + i * 16 + g;
            int colg = h * HDq + j * 8;
            size_t a0 = (size_t)(b * Sq + r) * Dq + colg;
            size_t a1 = (size_t)(b * Sq + r + 8) * Dq + colg;
            g_att[a0 + p0c] = tf32r(oacc[i][j][0] * il0);
            g_att[a0 + p1c] = tf32r(oacc[i][j][1] * il0);
            g_att[a1 + p0c] = tf32r(oacc[i][j][2] * il1);
            g_att[a1 + p1c] = tf32r(oacc[i][j][3] * il1);
        }
    }
}

// ---------------------------------------------------------------------------
// Launch.  Input order: xq, xv, xk, Wq, bq, Wk, bk, Wv, bv, Wo, bo
// ---------------------------------------------------------------------------
extern "C" void kernel_launch(void* const* d_in, const int* in_sizes, int n_in,
                              void* d_out, int out_size)
{
    const float* xq = (const float*)d_in[0];
    const float* xv = (const float*)d_in[1];
    const float* xk = (const float*)d_in[2];
    const float* Wq = (const float*)d_in[3];
    const float* bq = (const float*)d_in[4];
    const float* Wk = (const float*)d_in[5];
    const float* bk = (const float*)d_in[6];
    const float* Wv = (const float*)d_in[7];
    const float* bv = (const float*)d_in[8];
    const float* Wo = (const float*)d_in[9];
    const float* bo = (const float*)d_in[10];
    float* out = (float*)d_out;

    float *pq, *pk, *pv, *patt, *prx, *prw;
    cudaGetSymbolAddress((void**)&pq, g_q);
    cudaGetSymbolAddress((void**)&pk, g_k);
    cudaGetSymbolAddress((void**)&pv, g_v);
    cudaGetSymbolAddress((void**)&patt, g_att);
    cudaGetSymbolAddress((void**)&prx, g_rx);
    cudaGetSymbolAddress((void**)&prw, g_rw);

    static int attr_done = 0;
    if (!attr_done) {
        cudaFuncSetAttribute(gemm_cp,
            cudaFuncAttributeMaxDynamicSharedMemorySize, GEMM_SMEM);
        cudaFuncSetAttribute(attn_mma,
            cudaFuncAttributeMaxDynamicSharedMemorySize, ATTN_SMEM);
        attr_done = 1;
    }

    // Pre-round + interleave inputs and weights to tf32
    dim3 ground(1024, 7);
    round_tf32<<<ground, 256>>>(xq, xk, xv, Wq, Wk, Wv, Wo);

    const float* rxq = prx + 0 * (size_t)Mq * Dq;
    const float* rxk = prx + 1 * (size_t)Mq * Dq;
    const float* rxv = prx + 2 * (size_t)Mq * Dq;
    const float* rwq = prw + 0 * (size_t)Dq * Dq;
    const float* rwk = prw + 1 * (size_t)Dq * Dq;
    const float* rwv = prw + 2 * (size_t)Dq * Dq;
    const float* rwo = prw + 3 * (size_t)Dq * Dq;

    // Fused Q/K/V projections
    dim3 gqkv(Dq / 128, Mq / 128, 3);     // (8, 32, 3)
    gemm_cp<<<gqkv, 256, GEMM_SMEM>>>(
        rxq, rwq, bq, pq,
        rxk, rwk, bk, pk,
        rxv, rwv, bv, pv, 1);

    dim3 gattn(Sq / 128, Bq * Hq);        // (16, 32)
    attn_mma<<<gattn, 128, ATTN_SMEM>>>();

    // Output projection (A = g_att interleaved, W = rwo interleaved)
    dim3 gproj(Dq / 128, Mq / 128, 1);    // (8, 32)
    gemm_cp<<<gproj, 256, GEMM_SMEM>>>(
        patt, rwo, bo, out,
        patt, rwo, bo, out,
        patt, rwo, bo, out, 0);
}

// round 14
// speedup vs baseline: 2.0816x; 1.0004x over previous
#include <cuda_runtime.h>
#include <cstdint>

// Problem constants
#define Bq 2
#define Sq 2048
#define Dq 1024
#define Hq 16
#define HDq 64
#define Mq (Bq * Sq)   // 4096
#define GK Dq          // 1024

// Interleave within 8-groups: logical u -> ((u&3)*2)|(u>>2)  (t, t+4 adjacent)
__device__ __forceinline__ int perm8(int u) { return ((u & 3) << 1) | (u >> 2); }
__device__ __forceinline__ int spos(int s)  { return (s & ~7) | perm8(s & 7); }

// Scratch (device globals: allocation-free)
__device__ float g_q[Bq * Hq * Sq * HDq];    // [b][h][s][hd-perm]
__device__ float g_k[Bq * Hq * Sq * HDq];    // [b][h][s][hd-perm]
__device__ float g_v[Bq * Hq * Sq * HDq];    // [b][h][hd][s-perm]  (transposed!)
__device__ float g_att[Mq * Dq];             // [b*s][d-perm]
__device__ float g_rx[3][Mq * Dq];           // perm-rounded xq, xk, xv
__device__ float g_rw[4][Dq * Dq];           // perm-rounded Wq, Wk, Wv, Wo

// ---------------------------------------------------------------------------
// Helpers
// ---------------------------------------------------------------------------
__device__ __forceinline__ float tf32r(float x) {
    unsigned u;
    asm("cvt.rna.tf32.f32 %0, %1;" : "=r"(u) : "f"(x));
    return __uint_as_float(u);
}

__device__ __forceinline__ void mma_tf32(float c[4], const unsigned a[4],
                                         const unsigned b[2]) {
    asm volatile(
        "mma.sync.aligned.m16n8k8.row.col.f32.tf32.tf32.f32 "
        "{%0,%1,%2,%3}, {%4,%5,%6,%7}, {%8,%9}, {%0,%1,%2,%3};\n"
        : "+f"(c[0]), "+f"(c[1]), "+f"(c[2]), "+f"(c[3])
        : "r"(a[0]), "r"(a[1]), "r"(a[2]), "r"(a[3]),
          "r"(b[0]), "r"(b[1]));
}

__device__ __forceinline__ uint32_t s2u(const void* p) {
    uint32_t a;
    asm("{ .reg .u64 t; cvta.to.shared.u64 t, %1; cvt.u32.u64 %0, t; }"
        : "=r"(a) : "l"(p));
    return a;
}

__device__ __forceinline__ void cp16(uint32_t dst, const void* src) {
    asm volatile("cp.async.cg.shared.global [%0], [%1], 16;"
                 :: "r"(dst), "l"(src) : "memory");
}
#define CP_COMMIT() asm volatile("cp.async.commit_group;" ::: "memory")
#define CP_WAIT0()  asm volatile("cp.async.wait_group 0;" ::: "memory")
#define CP_WAIT1()  asm volatile("cp.async.wait_group 1;" ::: "memory")

// ---------------------------------------------------------------------------
// Pre-round + column-interleave inputs/weights to tf32 (rna), once per launch.
// out per 8-group = (x0,x4,x1,x5),(x2,x6,x3,x7).
// ---------------------------------------------------------------------------
__global__ __launch_bounds__(256) void round_tf32(
    const float* xq, const float* xk, const float* xv,
    const float* wq, const float* wk, const float* wv, const float* wo)
{
    const float* src; float* dst; int n8;
    switch (blockIdx.y) {
        case 0: src = xq; dst = g_rx[0]; n8 = Mq * Dq / 8; break;
        case 1: src = xk; dst = g_rx[1]; n8 = Mq * Dq / 8; break;
        case 2: src = xv; dst = g_rx[2]; n8 = Mq * Dq / 8; break;
        case 3: src = wq; dst = g_rw[0]; n8 = Dq * Dq / 8; break;
        case 4: src = wk; dst = g_rw[1]; n8 = Dq * Dq / 8; break;
        case 5: src = wv; dst = g_rw[2]; n8 = Dq * Dq / 8; break;
        default: src = wo; dst = g_rw[3]; n8 = Dq * Dq / 8; break;
    }
    for (int i = blockIdx.x * 256 + threadIdx.x; i < n8; i += gridDim.x * 256) {
        float4 v0 = ((const float4*)src)[2 * i];
        float4 v1 = ((const float4*)src)[2 * i + 1];
        ((float4*)dst)[2 * i]     = make_float4(tf32r(v0.x), tf32r(v1.x),
                                                tf32r(v0.y), tf32r(v1.y));
        ((float4*)dst)[2 * i + 1] = make_float4(tf32r(v0.z), tf32r(v1.z),
                                                tf32r(v0.w), tf32r(v1.w));
    }
}

// ===========================================================================
// TF32 GEMM, NT: C[m,n] = sum_k A[m,k]*W[n,k] + bias[n]
// A/W pre-rounded + interleaved. BM=BN=128, BK=32, 128 threads, 4 warps in
// 2x2, warp tile 64x64 (32 HMMA per 16 LDS.64 per k-step). 2-stage cp.async.
// mode 0: plain row-major C.  mode 1: z<2 -> [b][h][s][hd-perm] (Q/K);
//                             z==2 -> [b][h][hd][s-perm] (V transposed).
// ===========================================================================
#define GST 40
#define GEMM_SMEM (2 * 2 * 128 * GST * 4)   // 81920 B

__global__ __launch_bounds__(128) void gemm_cp(
    const float* A0, const float* W0, const float* B0, float* C0,
    const float* A1, const float* W1, const float* B1, float* C1,
    const float* A2, const float* W2, const float* B2, float* C2,
    int mode)
{
    extern __shared__ float sm[];
    const float* A; const float* W; const float* bias; float* C;
    if (blockIdx.z == 0)      { A = A0; W = W0; bias = B0; C = C0; }
    else if (blockIdx.z == 1) { A = A1; W = W1; bias = B1; C = C1; }
    else                      { A = A2; W = W2; bias = B2; C = C2; }

    const int tid  = threadIdx.x;
    const int warp = tid >> 5;        // 0..3
    const int lane = tid & 31;
    const int g    = lane >> 2;
    const int t    = lane & 3;
    const int wm   = (warp >> 1) * 64;
    const int wn   = (warp & 1) * 64;
    const int m0   = blockIdx.y * 128;
    const int n0   = blockIdx.x * 128;

    const uint32_t smu = s2u(sm);
    const float* pa = A + (size_t)m0 * GK;
    const float* pw = W + (size_t)n0 * GK;
    const int cr = tid >> 3;          // 0..15 (rows cr + 16q)
    const int cc = (tid & 7) * 4;

    float acc[4][8][4] = {};

    #define STAGE(it_, buf_)                                                   \
    do {                                                                       \
        const int kk = (it_) * 32;                                             \
        const uint32_t sa = smu + (uint32_t)(buf_) * (2 * 128 * GST * 4);      \
        const uint32_t sw = sa + 128 * GST * 4;                                \
        _Pragma("unroll")                                                      \
        for (int q = 0; q < 8; q++) {                                          \
            int r = cr + q * 16;                                               \
            cp16(sa + (r * GST + cc) * 4, pa + (size_t)r * GK + kk + cc);      \
            cp16(sw + (r * GST + cc) * 4, pw + (size_t)r * GK + kk + cc);      \
        }                                                                      \
    } while (0)

    STAGE(0, 0); CP_COMMIT();

    for (int it = 0; it < 32; it++) {
        __syncthreads();              // closes reads of buffer (it+1)&1
        if (it + 1 < 32) STAGE(it + 1, (it + 1) & 1);
        CP_COMMIT();
        CP_WAIT1();                   // stage `it` resident
        __syncthreads();

        const float* As = sm + (it & 1) * (2 * 128 * GST);
        const float* Ws = As + 128 * GST;
        #pragma unroll
        for (int ks = 0; ks < 4; ks++) {
            const int kc = ks * 8 + 2 * t;
            unsigned af[4][4];
            #pragma unroll
            for (int i = 0; i < 4; i++) {
                float2 p0 = *(const float2*)(As + (wm + i * 16 + g) * GST + kc);
                float2 p1 = *(const float2*)(As + (wm + i * 16 + g + 8) * GST + kc);
                af[i][0] = __float_as_uint(p0.x);
                af[i][1] = __float_as_uint(p1.x);
                af[i][2] = __float_as_uint(p0.y);
                af[i][3] = __float_as_uint(p1.y);
            }
            #pragma unroll
            for (int j = 0; j < 8; j++) {
                float2 pb = *(const float2*)(Ws + (wn + j * 8 + g) * GST + kc);
                unsigned bf[2] = { __float_as_uint(pb.x), __float_as_uint(pb.y) };
                #pragma unroll
                for (int i = 0; i < 4; i++)
                    mma_tf32(acc[i][j], af[i], bf);
            }
        }
    }
    #undef STAGE

    // Epilogue
    const int p0c = perm8(2 * t);
    const int p1c = perm8(2 * t + 1);
    const bool v_mode = (mode == 1) && (blockIdx.z == 2);
    #pragma unroll
    for (int i = 0; i < 4; i++) {
        #pragma unroll
        for (int j = 0; j < 8; j++) {
            int mrow = m0 + wm + i * 16 + g;
            int mr2  = mrow + 8;
            int ncol = n0 + wn + j * 8 + t * 2;
            float b0 = bias[ncol], b1 = bias[ncol + 1];
            float2 lo = make_float2(acc[i][j][0] + b0, acc[i][j][1] + b1);
            float2 hi = make_float2(acc[i][j][2] + b0, acc[i][j][3] + b1);
            if (mode == 0) {
                *(float2*)(C + (size_t)mrow * GK + ncol) = lo;
                *(float2*)(C + (size_t)mr2 * GK + ncol) = hi;
            } else if (!v_mode) {
                // Q/K: [b][h][s][hd-perm], tf32-rounded
                int hh = ncol >> 6;
                int hdg = (ncol & 63) - 2 * t;
                size_t r0 = ((((size_t)(mrow >> 11) * Hq + hh) << 11)
                             + (mrow & 2047)) * HDq + hdg;
                size_t r1 = ((((size_t)(mr2 >> 11) * Hq + hh) << 11)
                             + (mr2 & 2047)) * HDq + hdg;
                C[r0 + p0c] = tf32r(lo.x);
                C[r0 + p1c] = tf32r(lo.y);
                C[r1 + p0c] = tf32r(hi.x);
                C[r1 + p1c] = tf32r(hi.y);
            } else {
                // V: [b][h][hd][s-perm], tf32-rounded
                int hh = ncol >> 6, hd0 = ncol & 63;
                size_t base0 = (((size_t)(mrow >> 11) * Hq + hh) * HDq + hd0) << 11;
                size_t base1 = (((size_t)(mr2 >> 11) * Hq + hh) * HDq + hd0) << 11;
                int sp0 = spos(mrow & 2047);
                int sp1 = spos(mr2 & 2047);
                C[base0 + sp0]            = tf32r(lo.x);
                C[base0 + (1 << 11) + sp0] = tf32r(lo.y);
                C[base1 + sp1]            = tf32r(hi.x);
                C[base1 + (1 << 11) + sp1] = tf32r(hi.y);
            }
        }
    }
}

// ===========================================================================
// TF32 flash attention: 128 queries/block, 4 warps x 32 rows, 64-key tiles,
// double-buffered cp.async. K: [key][hd-perm] (S b-frags LDS.64).
// V staged TRANSPOSED [hd][key-perm] -> PV b-frags are LDS.64 too.
// ===========================================================================
#define KST 72
#define VST 72
#define PST 68
#define AKV (64 * KST + 64 * VST)
#define ATTN_SMEM ((2 * AKV + 128 * PST) * 4)  // 108544 B

__global__ __launch_bounds__(128) void attn_mma()
{
    extern __shared__ float sm[];
    float* Ps = sm + 2 * AKV;

    const int bh   = blockIdx.y;
    const int q0   = blockIdx.x * 128;
    const int b    = bh >> 4;
    const int h    = bh & 15;
    const int tid  = threadIdx.x;
    const int warp = tid >> 5;
    const int lane = tid & 31;
    const int g    = lane >> 2;
    const int t    = lane & 3;
    const int wm   = warp * 32;

    const float* gq  = g_q + (((size_t)bh) << 11) * HDq;
    const float* gk  = g_k + (((size_t)bh) << 11) * HDq;
    const float* gvt = g_v + (((size_t)bh) << 17);   // [hd][s-perm]

    const uint32_t smu = s2u(sm);
    const uint32_t uPs = s2u(Ps);

    // K tile: [key][hd-perm]; V tile: [hd][key-perm] (rows = hd)
    #define STAGE_KV(tl_, bf_)                                                 \
    do {                                                                       \
        const uint32_t sk = smu + (uint32_t)(bf_) * (AKV * 4);                 \
        const uint32_t sv = sk + 64 * KST * 4;                                 \
        _Pragma("unroll")                                                      \
        for (int m = 0; m < 8; m++) {                                          \
            int idx = m * 128 + tid;                                           \
            int r = idx >> 4, c = (idx & 15) * 4;                              \
            cp16(sk + (r * KST + c) * 4,                                       \
                 gk + (size_t)((tl_) * 64 + r) * HDq + c);                     \
            cp16(sv + (r * VST + c) * 4,                                       \
                 gvt + ((size_t)r << 11) + (tl_) * 64 + c);                    \
        }                                                                      \
    } while (0)

    // ---- Stage Q (group A) and tile 0 K/V (group B) ----
    #pragma unroll
    for (int m = 0; m < 16; m++) {
        int idx = m * 128 + tid;
        int r = idx >> 4, c = (idx & 15) * 4;
        cp16(uPs + (r * PST + c) * 4, gq + (size_t)(q0 + r) * HDq + c);
    }
    CP_COMMIT();
    STAGE_KV(0, 0); CP_COMMIT();
    CP_WAIT1();
    __syncthreads();

    // Build Q fragments from interleaved pairs (x 0.125 exact)
    unsigned qa[2][8][4];
    #pragma unroll
    for (int i = 0; i < 2; i++)
        #pragma unroll
        for (int k = 0; k < 8; k++) {
            float2 p0 = *(const float2*)(Ps + (wm + i * 16 + g) * PST + k * 8 + 2 * t);
            float2 p1 = *(const float2*)(Ps + (wm + i * 16 + g + 8) * PST + k * 8 + 2 * t);
            qa[i][k][0] = __float_as_uint(p0.x * 0.125f);
            qa[i][k][1] = __float_as_uint(p1.x * 0.125f);
            qa[i][k][2] = __float_as_uint(p0.y * 0.125f);
            qa[i][k][3] = __float_as_uint(p1.y * 0.125f);
        }
    __syncthreads();

    float oacc[2][8][4] = {};
    float mrow[2][2] = { {-1e30f, -1e30f}, {-1e30f, -1e30f} };
    float lrow[2][2] = { {0.f, 0.f}, {0.f, 0.f} };

    for (int tile = 0; tile < Sq / 64; tile++) {
        if (tile + 1 < Sq / 64) {
            STAGE_KV(tile + 1, (tile + 1) & 1);
            CP_COMMIT();
            CP_WAIT1();
        } else {
            CP_WAIT0();
        }
        __syncthreads();

        const float* Ks = sm + (tile & 1) * AKV;
        const float* Vs = Ks + 64 * KST;

        // ---- S = Q K^T ----
        float sacc[2][8][4] = {};
        #pragma unroll
        for (int k = 0; k < 8; k++) {
            #pragma unroll
            for (int j = 0; j < 8; j++) {
                float2 pb = *(const float2*)(Ks + (j * 8 + g) * KST + k * 8 + 2 * t);
                unsigned bf[2] = { __float_as_uint(pb.x), __float_as_uint(pb.y) };
                mma_tf32(sacc[0][j], qa[0][k], bf);
                mma_tf32(sacc[1][j], qa[1][k], bf);
            }
        }

        // ---- Online softmax ----
        #pragma unroll
        for (int i = 0; i < 2; i++) {
            float mx0 = -1e30f, mx1 = -1e30f;
            #pragma unroll
            for (int j = 0; j < 8; j++) {
                mx0 = fmaxf(mx0, fmaxf(sacc[i][j][0], sacc[i][j][1]));
                mx1 = fmaxf(mx1, fmaxf(sacc[i][j][2], sacc[i][j][3]));
            }
            mx0 = fmaxf(mx0, __shfl_xor_sync(0xffffffffu, mx0, 1));
            mx0 = fmaxf(mx0, __shfl_xor_sync(0xffffffffu, mx0, 2));
            mx1 = fmaxf(mx1, __shfl_xor_sync(0xffffffffu, mx1, 1));
            mx1 = fmaxf(mx1, __shfl_xor_sync(0xffffffffu, mx1, 2));

            float nm0 = fmaxf(mrow[i][0], mx0), nm1 = fmaxf(mrow[i][1], mx1);
            float a0 = __expf(mrow[i][0] - nm0), a1 = __expf(mrow[i][1] - nm1);
            mrow[i][0] = nm0; mrow[i][1] = nm1;

            float ps0 = 0.f, ps1 = 0.f;
            #pragma unroll
            for (int j = 0; j < 8; j++) {
                sacc[i][j][0] = __expf(sacc[i][j][0] - nm0);
                sacc[i][j][1] = __expf(sacc[i][j][1] - nm0);
                sacc[i][j][2] = __expf(sacc[i][j][2] - nm1);
                sacc[i][j][3] = __expf(sacc[i][j][3] - nm1);
                ps0 += sacc[i][j][0] + sacc[i][j][1];
                ps1 += sacc[i][j][2] + sacc[i][j][3];
            }
            ps0 += __shfl_xor_sync(0xffffffffu, ps0, 1);
            ps0 += __shfl_xor_sync(0xffffffffu, ps0, 2);
            ps1 += __shfl_xor_sync(0xffffffffu, ps1, 1);
            ps1 += __shfl_xor_sync(0xffffffffu, ps1, 2);
            lrow[i][0] = lrow[i][0] * a0 + ps0;
            lrow[i][1] = lrow[i][1] * a1 + ps1;

            #pragma unroll
            for (int j = 0; j < 8; j++) {
                oacc[i][j][0] *= a0; oacc[i][j][1] *= a0;
                oacc[i][j][2] *= a1; oacc[i][j][3] *= a1;
            }
        }

        // ---- Store P (tf32) into Ps, plain layout (warp-private rows) ----
        #pragma unroll
        for (int i = 0; i < 2; i++)
            #pragma unroll
            for (int j = 0; j < 8; j++) {
                *(float2*)(Ps + (wm + i * 16 + g) * PST + j * 8 + 2 * t) =
                    make_float2(tf32r(sacc[i][j][0]), tf32r(sacc[i][j][1]));
                *(float2*)(Ps + (wm + i * 16 + g + 8) * PST + j * 8 + 2 * t) =
                    make_float2(tf32r(sacc[i][j][2]), tf32r(sacc[i][j][3]));
            }
        __syncwarp();

        // ---- O += P V : transposed V, b-frag pairs as LDS.64 ----
        #pragma unroll
        for (int k = 0; k < 8; k++) {
            unsigned pa[2][4];
            #pragma unroll
            for (int i = 0; i < 2; i++) {
                const float* pr0 = Ps + (wm + i * 16 + g) * PST + k * 8;
                const float* pr1 = pr0 + 8 * PST;
                pa[i][0] = __float_as_uint(pr0[t]);
                pa[i][1] = __float_as_uint(pr1[t]);
                pa[i][2] = __float_as_uint(pr0[t + 4]);
                pa[i][3] = __float_as_uint(pr1[t + 4]);
            }
            #pragma unroll
            for (int j = 0; j < 8; j++) {
                float2 vb = *(const float2*)(Vs + (j * 8 + g) * VST + k * 8 + 2 * t);
                unsigned bf[2] = { __float_as_uint(vb.x), __float_as_uint(vb.y) };
                mma_tf32(oacc[0][j], pa[0], bf);
                mma_tf32(oacc[1][j], pa[1], bf);
            }
        }
        __syncthreads();
    }
    #undef STAGE_KV

    // ---- Epilogue: tf32-rounded O / l, interleaved positions ----
    const int p0c = perm8(2 * t);
    const int p1c = perm8(2 * t + 1);
    #pragma unroll
    for (int i = 0; i < 2; i++) {
        float il0 = 1.0f / lrow[i][0], il1 = 1.0f / lrow[i][1];
        #pragma unroll
        for (int j = 0; j < 8; j++) {
            int r = q0 + wm + i * 16 + g;
            int colg = h * HDq + j * 8;
            size_t a0 = (size_t)(b * Sq + r) * Dq + colg;
            size_t a1 = (size_t)(b * Sq + r + 8) * Dq + colg;
            g_att[a0 + p0c] = tf32r(oacc[i][j][0] * il0);
            g_att[a0 + p1c] = tf32r(oacc[i][j][1] * il0);
            g_att[a1 + p0c] = tf32r(oacc[i][j][2] * il1);
            g_att[a1 + p1c] = tf32r(oacc[i][j][3] * il1);
        }
    }
}

// ---------------------------------------------------------------------------
// Launch.  Input order: xq, xv, xk, Wq, bq, Wk, bk, Wv, bv, Wo, bo
// ---------------------------------------------------------------------------
extern "C" void kernel_launch(void* const* d_in, const int* in_sizes, int n_in,
                              void* d_out, int out_size)
{
    const float* xq = (const float*)d_in[0];
    const float* xv = (const float*)d_in[1];
    const float* xk = (const float*)d_in[2];
    const float* Wq = (const float*)d_in[3];
    const float* bq = (const float*)d_in[4];
    const float* Wk = (const float*)d_in[5];
    const float* bk = (const float*)d_in[6];
    const float* Wv = (const float*)d_in[7];
    const float* bv = (const float*)d_in[8];
    const float* Wo = (const float*)d_in[9];
    const float* bo = (const float*)d_in[10];
    float* out = (float*)d_out;

    float *pq, *pk, *pv, *patt, *prx, *prw;
    cudaGetSymbolAddress((void**)&pq, g_q);
    cudaGetSymbolAddress((void**)&pk, g_k);
    cudaGetSymbolAddress((void**)&pv, g_v);
    cudaGetSymbolAddress((void**)&patt, g_att);
    cudaGetSymbolAddress((void**)&prx, g_rx);
    cudaGetSymbolAddress((void**)&prw, g_rw);

    static int attr_done = 0;
    if (!attr_done) {
        cudaFuncSetAttribute(gemm_cp,
            cudaFuncAttributeMaxDynamicSharedMemorySize, GEMM_SMEM);
        cudaFuncSetAttribute(attn_mma,
            cudaFuncAttributeMaxDynamicSharedMemorySize, ATTN_SMEM);
        attr_done = 1;
    }

    // Pre-round + interleave inputs and weights to tf32
    dim3 ground(1024, 7);
    round_tf32<<<ground, 256>>>(xq, xk, xv, Wq, Wk, Wv, Wo);

    const float* rxq = prx + 0 * (size_t)Mq * Dq;
    const float* rxk = prx + 1 * (size_t)Mq * Dq;
    const float* rxv = prx + 2 * (size_t)Mq * Dq;
    const float* rwq = prw + 0 * (size_t)Dq * Dq;
    const float* rwk = prw + 1 * (size_t)Dq * Dq;
    const float* rwv = prw + 2 * (size_t)Dq * Dq;
    const float* rwo = prw + 3 * (size_t)Dq * Dq;

    // Fused Q/K/V projections (z: 0=Q, 1=K, 2=V-transposed)
    dim3 gqkv(Dq / 128, Mq / 128, 3);     // (8, 32, 3)
    gemm_cp<<<gqkv, 128, GEMM_SMEM>>>(
        rxq, rwq, bq, pq,
        rxk, rwk, bk, pk,
        rxv, rwv, bv, pv, 1);

    dim3 gattn(Sq / 128, Bq * Hq);        // (16, 32)
    attn_mma<<<gattn, 128, ATTN_SMEM>>>();

    // Output projection
    dim3 gproj(Dq / 128, Mq / 128, 1);    // (8, 32)
    gemm_cp<<<gproj, 128, GEMM_SMEM>>>(
        patt, rwo, bo, out,
        patt, rwo, bo, out,
        patt, rwo, bo, out, 0);
}